// round 9
// baseline (speedup 1.0000x reference)
#include <cuda_runtime.h>
#include <cuda_bf16.h>
#include <math.h>
#include <float.h>

#define Bz 8
#define Cc 192
#define Nn 1568
#define NP 1664            /* 13*128 */
#define BNN (Bz*Nn)        /* 12544 = 98*128 */
#define KK 9
#define NBLK 13
#define NPAIR (NBLK*(NBLK+1)/2)     /* 91 */
#define DIST_CTAS (NPAIR*Bz)        /* 728 */
#define G1_CTAS (6*98)              /* 588 */

// smem tile geometry for the MMA GEMM (128-row tiles)
#define BK 32
#define TROW_B 80                /* bytes per smem row: 40 bf16 (32 + 8 pad) */
#define TILE_B (128*TROW_B)      /* 10240 bytes per operand tile */
#define STAGE_B (4*TILE_B)       /* Ah, Al, Bh, Bl */
#define GSMEM (2*STAGE_B)        /* 81920 bytes */

// ---- fused tail kernel (M=64 tiles) smem layout ----
#define ATILE_B (64*TROW_B)               /* 5120 */
#define STG_A   (2*ATILE_B + 2*TILE_B)    /* 30720: gh, gl, w1h, w1l */
#define PIPE_B  (2*STG_A)                 /* 61440 */
#define OFF_H   PIPE_B                    /* persistent h hi: 6 x ATILE_B */
#define OFF_L   (PIPE_B + 6*ATILE_B)      /* persistent h lo */
#define SM_TAIL (OFF_L + 6*ATILE_B)       /* 122880 */
#define B_STG2  (2*TILE_B)                /* phase-B stage: w2h, w2l */

// ---------------- scratch (static device globals; no allocation) ----------------
__device__ __align__(256) __nv_bfloat16 d_xn_hi[(size_t)Bz*NP*Cc], d_xn_lo[(size_t)Bz*NP*Cc];
__device__ __align__(256) __nv_bfloat16 d_xf_hi[(size_t)BNN*Cc],   d_xf_lo[(size_t)BNN*Cc];
__device__ __align__(256) float d_sqp[Bz*NP];
__device__ __align__(256) float d_dist[(size_t)Bz*NP*NP];
__device__ __align__(256) __nv_bfloat16 d_wuv_hi[768*Cc], d_wuv_lo[768*Cc];
__device__ __align__(256) __nv_bfloat16 d_w1_hi[256*384], d_w1_lo[256*384];
__device__ __align__(256) __nv_bfloat16 d_w2_hi[256*Cc],  d_w2_lo[256*Cc];
__device__ __align__(256) float d_c1[Cc], d_c2[Cc];
__device__ __align__(256) float d_Yt[(size_t)BNN*768];
__device__ __align__(256) __nv_bfloat16 d_g_hi[(size_t)BNN*384], d_g_lo[(size_t)BNN*384];

// ---------------- PTX helpers ----------------
__device__ __forceinline__ unsigned smem_u32(const void* p) {
    unsigned a;
    asm("{ .reg .u64 t; cvta.to.shared.u64 t, %1; cvt.u32.u64 %0, t; }" : "=r"(a) : "l"(p));
    return a;
}
__device__ __forceinline__ void cpa16(unsigned s, const void* g) {
    asm volatile("cp.async.cg.shared.global [%0], [%1], 16;" :: "r"(s), "l"(g));
}
#define CP_COMMIT() asm volatile("cp.async.commit_group;" ::: "memory")
#define CP_WAIT(n)  asm volatile("cp.async.wait_group %0;" :: "n"(n) : "memory")

__device__ __forceinline__ void ldm4(unsigned* r, unsigned a) {
    asm volatile("ldmatrix.sync.aligned.m8n8.x4.shared.b16 {%0,%1,%2,%3}, [%4];"
        : "=r"(r[0]), "=r"(r[1]), "=r"(r[2]), "=r"(r[3]) : "r"(a));
}
__device__ __forceinline__ void mma_bf16(float* c, const unsigned* a, const unsigned* b) {
    asm volatile("mma.sync.aligned.m16n8k16.row.col.f32.bf16.bf16.f32 "
        "{%0,%1,%2,%3}, {%4,%5,%6,%7}, {%8,%9}, {%0,%1,%2,%3};"
        : "+f"(c[0]), "+f"(c[1]), "+f"(c[2]), "+f"(c[3])
        : "r"(a[0]), "r"(a[1]), "r"(a[2]), "r"(a[3]), "r"(b[0]), "r"(b[1]));
}

__device__ __forceinline__ void split_store(float v, __nv_bfloat16* hi, __nv_bfloat16* lo, size_t i) {
    __nv_bfloat16 h = __float2bfloat16(v);
    hi[i] = h;
    lo[i] = __float2bfloat16(v - __bfloat162float(h));
}

// ---------------- fused prep: xf blocks | weight blocks | pad blocks ----------------
__global__ void prep_all(const float* __restrict__ x, const float* __restrict__ pos,
                         const float* __restrict__ We, const float* __restrict__ W1,
                         const float* __restrict__ b1, const float* __restrict__ g1,
                         const float* __restrict__ bb1, const float* __restrict__ W2,
                         const float* __restrict__ b2, const float* __restrict__ g2,
                         const float* __restrict__ bb2)
{
    int blk = blockIdx.x;
    int c = threadIdx.x;              // 192 threads
    if (blk < BNN) {
        int j = blk;
        int b = j / Nn, n = j - b*Nn;
        float v = x[((size_t)b*Cc + c)*Nn + n] + pos[n*Cc + c];
        split_store(v, d_xf_hi, d_xf_lo, (size_t)j*Cc + c);

        __shared__ float red[Cc];
        __shared__ float s_nrm;
        red[c] = v*v;
        __syncthreads();
        if (c < 64) red[c] += red[c+64] + red[c+128];
        __syncthreads();
        if (c < 32) {
            float s = red[c] + red[c+32];
            #pragma unroll
            for (int o = 16; o; o >>= 1) s += __shfl_xor_sync(0xffffffffu, s, o);
            if (c == 0) s_nrm = fmaxf(sqrtf(s), 1e-12f);
        }
        __syncthreads();
        float xn = v / s_nrm;
        split_store(xn, d_xn_hi, d_xn_lo, ((size_t)b*NP + n)*Cc + c);

        red[c] = xn*xn;
        __syncthreads();
        if (c < 64) red[c] += red[c+64] + red[c+128];
        __syncthreads();
        if (c < 32) {
            float s = red[c] + red[c+32];
            #pragma unroll
            for (int o = 16; o; o >>= 1) s += __shfl_xor_sync(0xffffffffu, s, o);
            if (c == 0) d_sqp[b*NP + n] = s;
        }
    } else if (blk < BNN + 768) {
        int i = (blk - BNN)*192 + c;
        const float denom = (float)sqrt(1.0 + 1e-5);
        if (i < 768*Cc) {
            int o = i/Cc, cc = i - o*Cc;
            float v = (o < 384) ? (We[o*384 + cc] - We[o*384 + 192 + cc])
                                : We[(o-384)*384 + 192 + cc];
            split_store(v, d_wuv_hi, d_wuv_lo, i);
        }
        if (i < 256*384) {
            int o = i/384;
            float v = (o < 192) ? W1[i] * (g1[o]/denom) : 0.0f;
            split_store(v, d_w1_hi, d_w1_lo, i);
        }
        if (i < 256*192) {
            int o = i/192;
            float v = (o < 192) ? W2[i] * (g2[o]/denom) : 0.0f;
            split_store(v, d_w2_hi, d_w2_lo, i);
        }
        if (i < Cc) {
            d_c1[i] = b1[i]*(g1[i]/denom) + bb1[i];
            d_c2[i] = b2[i]*(g2[i]/denom) + bb2[i];
        }
    } else {
        int r = blk - BNN - 768;
        int b = r / (NP-Nn), pr = r - b*(NP-Nn);
        int row = Nn + pr;
        size_t i = ((size_t)b*NP + row)*Cc + c;
        d_xn_hi[i] = __float2bfloat16(0.0f);
        d_xn_lo[i] = __float2bfloat16(0.0f);
        if (c == 0) d_sqp[b*NP + row] = 1e30f;
    }
}

// ============ shared 128x128 mainloop (phase1 kernels) ============
template<int KDIM>
__device__ __forceinline__ void mma_mainloop(
    const __nv_bfloat16* const* srcs, const int* rbase,
    unsigned sb, int tid, int lane, int warp_m, int warp_n,
    float acc[4][4][4])
{
    constexpr int NCH = KDIM / BK;
    auto load_chunk = [&](int ch, int s) {
        unsigned so = sb + s*STAGE_B;
        int k0 = ch*BK;
        #pragma unroll
        for (int t = 0; t < 4; t++) {
            #pragma unroll
            for (int q = 0; q < 2; q++) {
                int v = tid + q*256;
                int row = v >> 2, c4 = v & 3;
                cpa16(so + t*TILE_B + row*TROW_B + c4*16,
                      srcs[t] + (size_t)(rbase[t] + row)*KDIM + k0 + c4*8);
            }
        }
    };

    load_chunk(0, 0);
    CP_COMMIT();

    #pragma unroll
    for (int ch = 0; ch < NCH; ch++) {
        if (ch + 1 < NCH) { load_chunk(ch+1, (ch+1)&1); CP_COMMIT(); CP_WAIT(1); }
        else              { CP_WAIT(0); }
        __syncthreads();

        unsigned so = sb + (ch&1)*STAGE_B;
        #pragma unroll
        for (int ks = 0; ks < 2; ks++) {
            unsigned ah[4][4], al[4][4], bh[4][2], bl[4][2];
            #pragma unroll
            for (int mt = 0; mt < 4; mt++) {
                unsigned ra = so + (warp_m*64 + mt*16 + (lane & 15))*TROW_B
                            + ks*32 + (lane >> 4)*16;
                ldm4(ah[mt], ra);
                ldm4(al[mt], ra + TILE_B);
            }
            #pragma unroll
            for (int p = 0; p < 2; p++) {
                int nrow = warp_n*32 + p*16 + (lane >> 4)*8 + (lane & 7);
                unsigned rb = so + 2*TILE_B + nrow*TROW_B + ks*32 + ((lane >> 3) & 1)*16;
                unsigned r4[4];
                ldm4(r4, rb);
                bh[2*p][0] = r4[0]; bh[2*p][1] = r4[1];
                bh[2*p+1][0] = r4[2]; bh[2*p+1][1] = r4[3];
                ldm4(r4, rb + TILE_B);
                bl[2*p][0] = r4[0]; bl[2*p][1] = r4[1];
                bl[2*p+1][0] = r4[2]; bl[2*p+1][1] = r4[3];
            }
            #pragma unroll
            for (int mt = 0; mt < 4; mt++)
                #pragma unroll
                for (int nt = 0; nt < 4; nt++) {
                    mma_bf16(acc[mt][nt], ah[mt], bh[nt]);
                    mma_bf16(acc[mt][nt], ah[mt], bl[nt]);
                    mma_bf16(acc[mt][nt], al[mt], bh[nt]);
                }
        }
        __syncthreads();
    }
}

// ---------------- phase1: dist (symmetric) + gemm1 (Yt) in ONE launch ----------------
__global__ void __launch_bounds__(256, 2) phase1()
{
    extern __shared__ char sm[];
    unsigned sb = smem_u32(sm);
    int tid = threadIdx.x, lane = tid & 31, wid = tid >> 5;
    int warp_m = wid & 1, warp_n = wid >> 1;
    int id = blockIdx.x;

    float acc[4][4][4];
    #pragma unroll
    for (int mt = 0; mt < 4; mt++)
        #pragma unroll
        for (int nt = 0; nt < 4; nt++)
            #pragma unroll
            for (int e = 0; e < 4; e++) acc[mt][nt][e] = 0.0f;

    float* stage = reinterpret_cast<float*>(sm);   // 128 x 33 floats

    if (id < DIST_CTAS) {
        int z = id / NPAIR;
        int p = id - z*NPAIR, by = 0;
        while (p >= NBLK - by) { p -= NBLK - by; by++; }
        int bx = by + p;
        int row0 = by*128, col0 = bx*128;

        size_t zo = (size_t)z*NP*Cc;
        const __nv_bfloat16* srcs[4] = {d_xn_hi + zo, d_xn_lo + zo, d_xn_hi + zo, d_xn_lo + zo};
        int rbase[4] = {row0, row0, col0, col0};
        mma_mainloop<Cc>(srcs, rbase, sb, tid, lane, warp_m, warp_n, acc);

        const float* sq = d_sqp + z*NP;
        float* dst = d_dist + (size_t)z*NP*NP;
        bool mirror = (bx != by);

        #pragma unroll 1
        for (int g = 0; g < 4; g++) {
            int cb = g*32;
            if (warp_n == g) {
                #pragma unroll
                for (int mt = 0; mt < 4; mt++) {
                    int r0 = warp_m*64 + mt*16 + (lane >> 2);
                    float s0 = sq[row0 + r0];
                    float s8 = sq[row0 + r0 + 8];
                    #pragma unroll
                    for (int nt = 0; nt < 4; nt++) {
                        int c0 = nt*8 + (lane & 3)*2;
                        stage[r0*33 + c0]     = s0 - 2.0f*acc[mt][nt][0];
                        stage[r0*33 + c0 + 1] = s0 - 2.0f*acc[mt][nt][1];
                        stage[(r0+8)*33 + c0]     = s8 - 2.0f*acc[mt][nt][2];
                        stage[(r0+8)*33 + c0 + 1] = s8 - 2.0f*acc[mt][nt][3];
                    }
                }
            }
            __syncthreads();
            {
                float sqc = sq[col0 + cb + lane];
                #pragma unroll 4
                for (int rr = 0; rr < 16; rr++) {
                    int r = wid*16 + rr;
                    dst[(size_t)(row0 + r)*NP + col0 + cb + lane] = stage[r*33 + lane] + sqc;
                }
            }
            if (mirror) {
                #pragma unroll
                for (int q = 0; q < 4; q++) {
                    int cc = wid*4 + q;
                    float sqc = sq[col0 + cb + cc];
                    #pragma unroll
                    for (int it = 0; it < 4; it++) {
                        int r = it*32 + lane;
                        dst[(size_t)(col0 + cb + cc)*NP + row0 + r] = stage[r*33 + cc] + sqc;
                    }
                }
            }
            __syncthreads();
        }
    } else {
        int t = id - DIST_CTAS;
        int by = t / 6, bx = t - by*6;
        int row0 = by*128, col0 = bx*128;

        const __nv_bfloat16* srcs[4] = {d_xf_hi, d_xf_lo, d_wuv_hi, d_wuv_lo};
        int rbase[4] = {row0, row0, col0, col0};
        mma_mainloop<Cc>(srcs, rbase, sb, tid, lane, warp_m, warp_n, acc);

        #pragma unroll 1
        for (int g = 0; g < 4; g++) {
            int cb = g*32;
            if (warp_n == g) {
                #pragma unroll
                for (int mt = 0; mt < 4; mt++) {
                    int r0 = warp_m*64 + mt*16 + (lane >> 2);
                    #pragma unroll
                    for (int nt = 0; nt < 4; nt++) {
                        int c0 = nt*8 + (lane & 3)*2;
                        stage[r0*33 + c0]     = acc[mt][nt][0];
                        stage[r0*33 + c0 + 1] = acc[mt][nt][1];
                        stage[(r0+8)*33 + c0]     = acc[mt][nt][2];
                        stage[(r0+8)*33 + c0 + 1] = acc[mt][nt][3];
                    }
                }
            }
            __syncthreads();
            #pragma unroll 4
            for (int rr = 0; rr < 16; rr++) {
                int r = wid*16 + rr;
                d_Yt[(size_t)(row0 + r)*768 + col0 + cb + lane] = stage[r*33 + lane];
            }
            __syncthreads();
        }
    }
}

// ---------------- fused tail (M=64 tiles, grid 196) ----------------
// phase A: h = relu(g.W1^T + c1) for 64 rows, kept split-bf16 in smem
// phase B: out = relu(h.W2^T + c2) + h, A from smem
__global__ void __launch_bounds__(256) mma_tail(float* __restrict__ outp)
{
    extern __shared__ char sm[];
    unsigned sb = smem_u32(sm);
    int tid = threadIdx.x, lane = tid & 31, wid = tid >> 5;
    int warp_m = wid & 1, warp_n = wid >> 1;
    int row0 = blockIdx.x*64;

    float acc[2][4][4];
    float* stage = reinterpret_cast<float*>(sm);   // 64 x 33 floats (epilogue)

    // ================= phase A: two 128-col passes, K=384 =================
    #pragma unroll 1
    for (int p = 0; p < 2; p++) {
        #pragma unroll
        for (int mt = 0; mt < 2; mt++)
            #pragma unroll
            for (int nt = 0; nt < 4; nt++)
                #pragma unroll
                for (int e = 0; e < 4; e++) acc[mt][nt][e] = 0.0f;

        int colbase = p*128;
        auto load_A = [&](int ch, int s) {
            unsigned so = sb + s*STG_A;
            int k0 = ch*BK;
            {   // g hi/lo: 64 rows, 256 uint4 each
                int row = tid >> 2, c4 = tid & 3;
                cpa16(so + row*TROW_B + c4*16,
                      d_g_hi + (size_t)(row0 + row)*384 + k0 + c4*8);
                cpa16(so + ATILE_B + row*TROW_B + c4*16,
                      d_g_lo + (size_t)(row0 + row)*384 + k0 + c4*8);
            }
            #pragma unroll
            for (int q = 0; q < 2; q++) {   // w1 hi/lo: 128 rows
                int v = tid + q*256;
                int row = v >> 2, c4 = v & 3;
                cpa16(so + 2*ATILE_B + row*TROW_B + c4*16,
                      d_w1_hi + (size_t)(colbase + row)*384 + k0 + c4*8);
                cpa16(so + 2*ATILE_B + TILE_B + row*TROW_B + c4*16,
                      d_w1_lo + (size_t)(colbase + row)*384 + k0 + c4*8);
            }
        };

        load_A(0, 0);
        CP_COMMIT();

        #pragma unroll
        for (int ch = 0; ch < 12; ch++) {
            if (ch + 1 < 12) { load_A(ch+1, (ch+1)&1); CP_COMMIT(); CP_WAIT(1); }
            else             { CP_WAIT(0); }
            __syncthreads();

            unsigned so = sb + (ch&1)*STG_A;
            #pragma unroll
            for (int ks = 0; ks < 2; ks++) {
                unsigned ah[2][4], al[2][4], bh[4][2], bl[4][2];
                #pragma unroll
                for (int mt = 0; mt < 2; mt++) {
                    unsigned ra = so + (warp_m*32 + mt*16 + (lane & 15))*TROW_B
                                + ks*32 + (lane >> 4)*16;
                    ldm4(ah[mt], ra);
                    ldm4(al[mt], ra + ATILE_B);
                }
                #pragma unroll
                for (int q = 0; q < 2; q++) {
                    int nrow = warp_n*32 + q*16 + (lane >> 4)*8 + (lane & 7);
                    unsigned rb = so + 2*ATILE_B + nrow*TROW_B + ks*32 + ((lane >> 3) & 1)*16;
                    unsigned r4[4];
                    ldm4(r4, rb);
                    bh[2*q][0] = r4[0]; bh[2*q][1] = r4[1];
                    bh[2*q+1][0] = r4[2]; bh[2*q+1][1] = r4[3];
                    ldm4(r4, rb + TILE_B);
                    bl[2*q][0] = r4[0]; bl[2*q][1] = r4[1];
                    bl[2*q+1][0] = r4[2]; bl[2*q+1][1] = r4[3];
                }
                #pragma unroll
                for (int mt = 0; mt < 2; mt++)
                    #pragma unroll
                    for (int nt = 0; nt < 4; nt++) {
                        mma_bf16(acc[mt][nt], ah[mt], bh[nt]);
                        mma_bf16(acc[mt][nt], ah[mt], bl[nt]);
                        mma_bf16(acc[mt][nt], al[mt], bh[nt]);
                    }
            }
            __syncthreads();
        }

        // fragments -> persistent split-h smem tiles (ldmatrix A chunk format)
        #pragma unroll
        for (int mt = 0; mt < 2; mt++) {
            int r0 = warp_m*32 + mt*16 + (lane >> 2);
            #pragma unroll
            for (int nt = 0; nt < 4; nt++) {
                int c0 = warp_n*32 + nt*8 + (lane & 3)*2;
                #pragma unroll
                for (int e = 0; e < 4; e++) {
                    int r  = r0 + ((e >> 1) << 3);
                    int gc = colbase + c0 + (e & 1);
                    if (gc < Cc) {
                        float v = fmaxf(acc[mt][nt][e] + d_c1[gc], 0.0f);
                        __nv_bfloat16 hh = __float2bfloat16(v);
                        unsigned off = (unsigned)(gc >> 5)*ATILE_B + r*TROW_B + (gc & 31)*2;
                        *reinterpret_cast<__nv_bfloat16*>(sm + OFF_H + off) = hh;
                        *reinterpret_cast<__nv_bfloat16*>(sm + OFF_L + off) =
                            __float2bfloat16(v - __bfloat162float(hh));
                    }
                }
            }
        }
        __syncthreads();
    }

    // ================= phase B: two 128-col passes, K=192, A from smem ==========
    #pragma unroll 1
    for (int p = 0; p < 2; p++) {
        #pragma unroll
        for (int mt = 0; mt < 2; mt++)
            #pragma unroll
            for (int nt = 0; nt < 4; nt++)
                #pragma unroll
                for (int e = 0; e < 4; e++) acc[mt][nt][e] = 0.0f;

        int colbase = p*128;
        auto load_B2 = [&](int ch, int s) {
            unsigned so = sb + s*B_STG2;
            int k0 = ch*BK;
            #pragma unroll
            for (int q = 0; q < 2; q++) {
                int v = tid + q*256;
                int row = v >> 2, c4 = v & 3;
                cpa16(so + row*TROW_B + c4*16,
                      d_w2_hi + (size_t)(colbase + row)*Cc + k0 + c4*8);
                cpa16(so + TILE_B + row*TROW_B + c4*16,
                      d_w2_lo + (size_t)(colbase + row)*Cc + k0 + c4*8);
            }
        };

        load_B2(0, 0);
        CP_COMMIT();

        #pragma unroll
        for (int ch = 0; ch < 6; ch++) {
            if (ch + 1 < 6) { load_B2(ch+1, (ch+1)&1); CP_COMMIT(); CP_WAIT(1); }
            else            { CP_WAIT(0); }
            __syncthreads();

            unsigned sob = sb + (ch&1)*B_STG2;
            unsigned soa = sb + OFF_H + (unsigned)ch*ATILE_B;
            #pragma unroll
            for (int ks = 0; ks < 2; ks++) {
                unsigned ah[2][4], al[2][4], bh[4][2], bl[4][2];
                #pragma unroll
                for (int mt = 0; mt < 2; mt++) {
                    unsigned ra = soa + (warp_m*32 + mt*16 + (lane & 15))*TROW_B
                                + ks*32 + (lane >> 4)*16;
                    ldm4(ah[mt], ra);
                    ldm4(al[mt], ra + 6*ATILE_B);
                }
                #pragma unroll
                for (int q = 0; q < 2; q++) {
                    int nrow = warp_n*32 + q*16 + (lane >> 4)*8 + (lane & 7);
                    unsigned rb = sob + nrow*TROW_B + ks*32 + ((lane >> 3) & 1)*16;
                    unsigned r4[4];
                    ldm4(r4, rb);
                    bh[2*q][0] = r4[0]; bh[2*q][1] = r4[1];
                    bh[2*q+1][0] = r4[2]; bh[2*q+1][1] = r4[3];
                    ldm4(r4, rb + TILE_B);
                    bl[2*q][0] = r4[0]; bl[2*q][1] = r4[1];
                    bl[2*q+1][0] = r4[2]; bl[2*q+1][1] = r4[3];
                }
                #pragma unroll
                for (int mt = 0; mt < 2; mt++)
                    #pragma unroll
                    for (int nt = 0; nt < 4; nt++) {
                        mma_bf16(acc[mt][nt], ah[mt], bh[nt]);
                        mma_bf16(acc[mt][nt], ah[mt], bl[nt]);
                        mma_bf16(acc[mt][nt], al[mt], bh[nt]);
                    }
            }
            __syncthreads();
        }

        // epilogue
        #pragma unroll 1
        for (int g = 0; g < 4; g++) {
            int cb = g*32;
            if (warp_n == g) {
                #pragma unroll
                for (int mt = 0; mt < 2; mt++) {
                    int r0 = warp_m*32 + mt*16 + (lane >> 2);
                    #pragma unroll
                    for (int nt = 0; nt < 4; nt++) {
                        int c0 = nt*8 + (lane & 3)*2;
                        stage[r0*33 + c0]     = acc[mt][nt][0];
                        stage[r0*33 + c0 + 1] = acc[mt][nt][1];
                        stage[(r0+8)*33 + c0]     = acc[mt][nt][2];
                        stage[(r0+8)*33 + c0 + 1] = acc[mt][nt][3];
                    }
                }
            }
            __syncthreads();
            #pragma unroll
            for (int q = 0; q < 4; q++) {
                int cc = wid*4 + q;
                int gc = colbase + cb + cc;
                if (gc < Cc) {
                    float c2v = d_c2[gc];
                    unsigned ob = (unsigned)(gc >> 5)*ATILE_B + (gc & 31)*2;
                    #pragma unroll
                    for (int it = 0; it < 2; it++) {
                        int r = it*32 + lane;
                        int gr = row0 + r;
                        unsigned off = ob + r*TROW_B;
                        float sc = __bfloat162float(*reinterpret_cast<__nv_bfloat16*>(sm + OFF_H + off))
                                 + __bfloat162float(*reinterpret_cast<__nv_bfloat16*>(sm + OFF_L + off));
                        float v = fmaxf(stage[r*33 + cc] + c2v, 0.0f) + sc;
                        int b = gr / Nn, n = gr - b*Nn;
                        outp[((size_t)b*Cc + gc)*Nn + n] = v;
                    }
                }
            }
            __syncthreads();
        }
    }
}

// ---------------- fused top-9 + gather_max ----------------
__device__ __forceinline__ unsigned fkey32(float v) {
    unsigned u = __float_as_uint(v);
    return (u & 0x80000000u) ? ~u : (u | 0x80000000u);
}

#define TK_CAP 128

__global__ void __launch_bounds__(128) topk_gather(const float* __restrict__ be)
{
    __shared__ unsigned long long kb_s[4][TK_CAP];
    __shared__ int ids[4][KK];
    int lane = threadIdx.x & 31;
    int w    = threadIdx.x >> 5;
    int row  = blockIdx.x*4 + w;
    int b = row / Nn, n = row - b*Nn;
    const float* dr = d_dist + ((size_t)b*NP + n)*NP;
    unsigned long long* kb = kb_s[w];

    float mv = FLT_MAX;
    #pragma unroll
    for (int i = 0; i < 13; i++) {
        float4 v = reinterpret_cast<const float4*>(dr)[i*32 + lane];
        mv = fminf(mv, fminf(fminf(v.x, v.y), fminf(v.z, v.w)));
    }

    float tau = 0.0f;
    float mm = mv;
    #pragma unroll
    for (int r = 0; r < 9; r++) {
        float v = mm;
        #pragma unroll
        for (int off = 16; off; off >>= 1) v = fminf(v, __shfl_xor_sync(0xffffffffu, v, off));
        unsigned bl = __ballot_sync(0xffffffffu, mm == v);
        int src = __ffs(bl) - 1;
        if (lane == src) mm = FLT_MAX;
        tau = v;
    }

    int cnt = 0;
    #pragma unroll 1
    for (int i = 0; i < 13; i++) {
        float4 v = reinterpret_cast<const float4*>(dr)[i*32 + lane];
        int mbase = (i*32 + lane)*4;
        float vv[4] = {v.x, v.y, v.z, v.w};
        #pragma unroll
        for (int c = 0; c < 4; c++) {
            bool pr = (vv[c] <= tau);
            unsigned msk = __ballot_sync(0xffffffffu, pr);
            if (pr) {
                int pos = cnt + __popc(msk & ((1u << lane) - 1u));
                if (pos < TK_CAP)
                    kb[pos] = ((unsigned long long)fkey32(vv[c]) << 32) | (unsigned)(mbase + c);
            }
            cnt += __popc(msk);
        }
    }

    if (cnt <= TK_CAP) {
        #pragma unroll 1
        for (int r = 0; r < 9; r++) {
            unsigned long long best = ~0ULL;
            #pragma unroll
            for (int s = 0; s < 4; s++) {
                int pp = lane + s*32;
                if (pp < cnt) { unsigned long long k = kb[pp]; if (k < best) best = k; }
            }
            #pragma unroll
            for (int off = 16; off; off >>= 1) {
                unsigned long long o = __shfl_xor_sync(0xffffffffu, best, off);
                if (o < best) best = o;
            }
            #pragma unroll
            for (int s = 0; s < 4; s++) {
                int pp = lane + s*32;
                if (pp < cnt && kb[pp] == best) kb[pp] = ~0ULL;
            }
            if (lane == 0) ids[w][r] = (int)(best & 0xffffffffu);
        }
    } else if (lane == 0) {
        unsigned long long bd[9];
        #pragma unroll
        for (int s = 0; s < 9; s++) bd[s] = ~0ULL;
        unsigned long long wk = ~0ULL; int ws = 0;
        for (int m2 = 0; m2 < NP; m2++) {
            unsigned long long k = ((unsigned long long)fkey32(dr[m2]) << 32) | (unsigned)m2;
            if (k < wk) {
                bd[ws] = k;
                wk = bd[0]; ws = 0;
                #pragma unroll
                for (int s = 1; s < 9; s++) if (bd[s] > wk) { wk = bd[s]; ws = s; }
            }
        }
        #pragma unroll
        for (int s = 0; s < 9; s++) ids[w][s] = (int)(bd[s] & 0xffffffffu);
    }

    __syncthreads();

    int tid = threadIdx.x;
    #pragma unroll 1
    for (int rw = 0; rw < 4; rw++) {
        int j = blockIdx.x*4 + rw;
        int bb = j / Nn;
        int base = bb*Nn;
        int id2[9];
        #pragma unroll
        for (int k = 0; k < 9; k++) id2[k] = ids[rw][k];
        #pragma unroll
        for (int it = 0; it < 3; it++) {
            int o = it*128 + tid;
            float m = -FLT_MAX;
            #pragma unroll
            for (int k = 0; k < 9; k++)
                m = fmaxf(m, d_Yt[(size_t)(base + id2[k])*768 + 384 + o]);
            float u = d_Yt[(size_t)j*768 + o] + be[o];
            float v = fmaxf(u + m, 0.0f);
            split_store(v, d_g_hi, d_g_lo, (size_t)j*384 + o);
        }
    }
}

// ---------------- launch ----------------
extern "C" void kernel_launch(void* const* d_in, const int* in_sizes, int n_in,
                              void* d_out, int out_size)
{
    const float* x   = (const float*)d_in[0];
    const float* pos = (const float*)d_in[1];
    const float* We  = (const float*)d_in[2];
    const float* be  = (const float*)d_in[3];
    const float* W1  = (const float*)d_in[4];
    const float* b1  = (const float*)d_in[5];
    const float* g1  = (const float*)d_in[6];
    const float* bb1 = (const float*)d_in[7];
    const float* W2  = (const float*)d_in[8];
    const float* b2  = (const float*)d_in[9];
    const float* g2  = (const float*)d_in[10];
    const float* bb2 = (const float*)d_in[11];
    float* out = (float*)d_out;

    cudaFuncSetAttribute(phase1,   cudaFuncAttributeMaxDynamicSharedMemorySize, GSMEM);
    cudaFuncSetAttribute(mma_tail, cudaFuncAttributeMaxDynamicSharedMemorySize, SM_TAIL);

    prep_all<<<BNN + 768 + Bz*(NP-Nn), 192>>>(x, pos, We, W1, b1, g1, bb1, W2, b2, g2, bb2);
    phase1<<<DIST_CTAS + G1_CTAS, 256, GSMEM>>>();
    topk_gather<<<BNN/4, 128>>>(be);
    mma_tail<<<BNN/64, 256, SM_TAIL>>>(out);
}

// round 10
// speedup vs baseline: 1.0814x; 1.0814x over previous
#include <cuda_runtime.h>
#include <cuda_bf16.h>
#include <math.h>
#include <float.h>

#define Bz 8
#define Cc 192
#define Nn 1568
#define NP 1664            /* 13*128 */
#define BNN (Bz*Nn)        /* 12544 = 98*128 */
#define KK 9
#define NBLK 13
#define NPAIR (NBLK*(NBLK+1)/2)     /* 91 */
#define DIST_CTAS (NPAIR*Bz)        /* 728 */
#define G1_CTAS (6*98)              /* 588 */

// smem tile geometry (128-row tiles)
#define BK 32
#define TROW_B 80                /* bytes per smem row: 40 bf16 (32 + 8 pad) */
#define TILE_B (128*TROW_B)      /* 10240 bytes per operand tile */
#define STAGE_B (4*TILE_B)       /* Ah, Al, Bh, Bl */
#define GSMEM (2*STAGE_B)        /* 81920 bytes */

// fused tail (M=128, 512 threads): pipeline + persistent split-h (6 chunks x hi/lo)
#define OFF_A2H GSMEM
#define OFF_A2L (GSMEM + 6*TILE_B)
#define SM_TAIL (GSMEM + 12*TILE_B)   /* 204800 */
#define B_STG2  (2*TILE_B)

// ---------------- scratch (static device globals; no allocation) ----------------
__device__ __align__(256) __nv_bfloat16 d_xn_hi[(size_t)Bz*NP*Cc], d_xn_lo[(size_t)Bz*NP*Cc];
__device__ __align__(256) __nv_bfloat16 d_xf_hi[(size_t)BNN*Cc],   d_xf_lo[(size_t)BNN*Cc];
__device__ __align__(256) float d_sqp[Bz*NP];
__device__ __align__(256) float d_dist[(size_t)Bz*NP*NP];
__device__ __align__(256) __nv_bfloat16 d_wuv_hi[768*Cc], d_wuv_lo[768*Cc];
__device__ __align__(256) __nv_bfloat16 d_w1_hi[256*384], d_w1_lo[256*384];
__device__ __align__(256) __nv_bfloat16 d_w2_hi[256*Cc],  d_w2_lo[256*Cc];
__device__ __align__(256) float d_c1[Cc], d_c2[Cc];
__device__ __align__(256) float d_Yt[(size_t)BNN*768];
__device__ __align__(256) __nv_bfloat16 d_g_hi[(size_t)BNN*384], d_g_lo[(size_t)BNN*384];

// ---------------- PTX helpers ----------------
__device__ __forceinline__ unsigned smem_u32(const void* p) {
    unsigned a;
    asm("{ .reg .u64 t; cvta.to.shared.u64 t, %1; cvt.u32.u64 %0, t; }" : "=r"(a) : "l"(p));
    return a;
}
__device__ __forceinline__ void cpa16(unsigned s, const void* g) {
    asm volatile("cp.async.cg.shared.global [%0], [%1], 16;" :: "r"(s), "l"(g));
}
#define CP_COMMIT() asm volatile("cp.async.commit_group;" ::: "memory")
#define CP_WAIT(n)  asm volatile("cp.async.wait_group %0;" :: "n"(n) : "memory")

__device__ __forceinline__ void ldm4(unsigned* r, unsigned a) {
    asm volatile("ldmatrix.sync.aligned.m8n8.x4.shared.b16 {%0,%1,%2,%3}, [%4];"
        : "=r"(r[0]), "=r"(r[1]), "=r"(r[2]), "=r"(r[3]) : "r"(a));
}
__device__ __forceinline__ void mma_bf16(float* c, const unsigned* a, const unsigned* b) {
    asm volatile("mma.sync.aligned.m16n8k16.row.col.f32.bf16.bf16.f32 "
        "{%0,%1,%2,%3}, {%4,%5,%6,%7}, {%8,%9}, {%0,%1,%2,%3};"
        : "+f"(c[0]), "+f"(c[1]), "+f"(c[2]), "+f"(c[3])
        : "r"(a[0]), "r"(a[1]), "r"(a[2]), "r"(a[3]), "r"(b[0]), "r"(b[1]));
}

__device__ __forceinline__ void split_store(float v, __nv_bfloat16* hi, __nv_bfloat16* lo, size_t i) {
    __nv_bfloat16 h = __float2bfloat16(v);
    hi[i] = h;
    lo[i] = __float2bfloat16(v - __bfloat162float(h));
}

// ---------------- fused prep: xf blocks | weight blocks | pad blocks ----------------
__global__ void prep_all(const float* __restrict__ x, const float* __restrict__ pos,
                         const float* __restrict__ We, const float* __restrict__ W1,
                         const float* __restrict__ b1, const float* __restrict__ g1,
                         const float* __restrict__ bb1, const float* __restrict__ W2,
                         const float* __restrict__ b2, const float* __restrict__ g2,
                         const float* __restrict__ bb2)
{
    int blk = blockIdx.x;
    int c = threadIdx.x;              // 192 threads
    if (blk < BNN) {
        int j = blk;
        int b = j / Nn, n = j - b*Nn;
        float v = x[((size_t)b*Cc + c)*Nn + n] + pos[n*Cc + c];
        split_store(v, d_xf_hi, d_xf_lo, (size_t)j*Cc + c);

        __shared__ float red[Cc];
        __shared__ float s_nrm;
        red[c] = v*v;
        __syncthreads();
        if (c < 64) red[c] += red[c+64] + red[c+128];
        __syncthreads();
        if (c < 32) {
            float s = red[c] + red[c+32];
            #pragma unroll
            for (int o = 16; o; o >>= 1) s += __shfl_xor_sync(0xffffffffu, s, o);
            if (c == 0) s_nrm = fmaxf(sqrtf(s), 1e-12f);
        }
        __syncthreads();
        float xn = v / s_nrm;
        split_store(xn, d_xn_hi, d_xn_lo, ((size_t)b*NP + n)*Cc + c);

        red[c] = xn*xn;
        __syncthreads();
        if (c < 64) red[c] += red[c+64] + red[c+128];
        __syncthreads();
        if (c < 32) {
            float s = red[c] + red[c+32];
            #pragma unroll
            for (int o = 16; o; o >>= 1) s += __shfl_xor_sync(0xffffffffu, s, o);
            if (c == 0) d_sqp[b*NP + n] = s;
        }
    } else if (blk < BNN + 768) {
        int i = (blk - BNN)*192 + c;
        const float denom = (float)sqrt(1.0 + 1e-5);
        if (i < 768*Cc) {
            int o = i/Cc, cc = i - o*Cc;
            float v = (o < 384) ? (We[o*384 + cc] - We[o*384 + 192 + cc])
                                : We[(o-384)*384 + 192 + cc];
            split_store(v, d_wuv_hi, d_wuv_lo, i);
        }
        if (i < 256*384) {
            int o = i/384;
            float v = (o < 192) ? W1[i] * (g1[o]/denom) : 0.0f;
            split_store(v, d_w1_hi, d_w1_lo, i);
        }
        if (i < 256*192) {
            int o = i/192;
            float v = (o < 192) ? W2[i] * (g2[o]/denom) : 0.0f;
            split_store(v, d_w2_hi, d_w2_lo, i);
        }
        if (i < Cc) {
            d_c1[i] = b1[i]*(g1[i]/denom) + bb1[i];
            d_c2[i] = b2[i]*(g2[i]/denom) + bb2[i];
        }
    } else {
        int r = blk - BNN - 768;
        int b = r / (NP-Nn), pr = r - b*(NP-Nn);
        int row = Nn + pr;
        size_t i = ((size_t)b*NP + row)*Cc + c;
        d_xn_hi[i] = __float2bfloat16(0.0f);
        d_xn_lo[i] = __float2bfloat16(0.0f);
        if (c == 0) d_sqp[b*NP + row] = 1e30f;
    }
}

// ============ shared 128x128 mainloop, 256 threads (phase1) ============
template<int KDIM>
__device__ __forceinline__ void mma_mainloop(
    const __nv_bfloat16* const* srcs, const int* rbase,
    unsigned sb, int tid, int lane, int warp_m, int warp_n,
    float acc[4][4][4])
{
    constexpr int NCH = KDIM / BK;
    auto load_chunk = [&](int ch, int s) {
        unsigned so = sb + s*STAGE_B;
        int k0 = ch*BK;
        #pragma unroll
        for (int t = 0; t < 4; t++) {
            #pragma unroll
            for (int q = 0; q < 2; q++) {
                int v = tid + q*256;
                int row = v >> 2, c4 = v & 3;
                cpa16(so + t*TILE_B + row*TROW_B + c4*16,
                      srcs[t] + (size_t)(rbase[t] + row)*KDIM + k0 + c4*8);
            }
        }
    };

    load_chunk(0, 0);
    CP_COMMIT();

    #pragma unroll
    for (int ch = 0; ch < NCH; ch++) {
        if (ch + 1 < NCH) { load_chunk(ch+1, (ch+1)&1); CP_COMMIT(); CP_WAIT(1); }
        else              { CP_WAIT(0); }
        __syncthreads();

        unsigned so = sb + (ch&1)*STAGE_B;
        #pragma unroll
        for (int ks = 0; ks < 2; ks++) {
            unsigned ah[4][4], al[4][4], bh[4][2], bl[4][2];
            #pragma unroll
            for (int mt = 0; mt < 4; mt++) {
                unsigned ra = so + (warp_m*64 + mt*16 + (lane & 15))*TROW_B
                            + ks*32 + (lane >> 4)*16;
                ldm4(ah[mt], ra);
                ldm4(al[mt], ra + TILE_B);
            }
            #pragma unroll
            for (int p = 0; p < 2; p++) {
                int nrow = warp_n*32 + p*16 + (lane >> 4)*8 + (lane & 7);
                unsigned rb = so + 2*TILE_B + nrow*TROW_B + ks*32 + ((lane >> 3) & 1)*16;
                unsigned r4[4];
                ldm4(r4, rb);
                bh[2*p][0] = r4[0]; bh[2*p][1] = r4[1];
                bh[2*p+1][0] = r4[2]; bh[2*p+1][1] = r4[3];
                ldm4(r4, rb + TILE_B);
                bl[2*p][0] = r4[0]; bl[2*p][1] = r4[1];
                bl[2*p+1][0] = r4[2]; bl[2*p+1][1] = r4[3];
            }
            #pragma unroll
            for (int mt = 0; mt < 4; mt++)
                #pragma unroll
                for (int nt = 0; nt < 4; nt++) {
                    mma_bf16(acc[mt][nt], ah[mt], bh[nt]);
                    mma_bf16(acc[mt][nt], ah[mt], bl[nt]);
                    mma_bf16(acc[mt][nt], al[mt], bh[nt]);
                }
        }
        __syncthreads();
    }
}

// ---------------- phase1: dist (symmetric) + gemm1 (Yt) in ONE launch ----------------
__global__ void __launch_bounds__(256, 2) phase1()
{
    extern __shared__ char sm[];
    unsigned sb = smem_u32(sm);
    int tid = threadIdx.x, lane = tid & 31, wid = tid >> 5;
    int warp_m = wid & 1, warp_n = wid >> 1;
    int id = blockIdx.x;

    float acc[4][4][4];
    #pragma unroll
    for (int mt = 0; mt < 4; mt++)
        #pragma unroll
        for (int nt = 0; nt < 4; nt++)
            #pragma unroll
            for (int e = 0; e < 4; e++) acc[mt][nt][e] = 0.0f;

    float* stage = reinterpret_cast<float*>(sm);   // 128 x 33 floats

    if (id < DIST_CTAS) {
        int z = id / NPAIR;
        int p = id - z*NPAIR, by = 0;
        while (p >= NBLK - by) { p -= NBLK - by; by++; }
        int bx = by + p;
        int row0 = by*128, col0 = bx*128;

        size_t zo = (size_t)z*NP*Cc;
        const __nv_bfloat16* srcs[4] = {d_xn_hi + zo, d_xn_lo + zo, d_xn_hi + zo, d_xn_lo + zo};
        int rbase[4] = {row0, row0, col0, col0};
        mma_mainloop<Cc>(srcs, rbase, sb, tid, lane, warp_m, warp_n, acc);

        const float* sq = d_sqp + z*NP;
        float* dst = d_dist + (size_t)z*NP*NP;
        bool mirror = (bx != by);

        #pragma unroll 1
        for (int g = 0; g < 4; g++) {
            int cb = g*32;
            if (warp_n == g) {
                #pragma unroll
                for (int mt = 0; mt < 4; mt++) {
                    int r0 = warp_m*64 + mt*16 + (lane >> 2);
                    float s0 = sq[row0 + r0];
                    float s8 = sq[row0 + r0 + 8];
                    #pragma unroll
                    for (int nt = 0; nt < 4; nt++) {
                        int c0 = nt*8 + (lane & 3)*2;
                        stage[r0*33 + c0]     = s0 - 2.0f*acc[mt][nt][0];
                        stage[r0*33 + c0 + 1] = s0 - 2.0f*acc[mt][nt][1];
                        stage[(r0+8)*33 + c0]     = s8 - 2.0f*acc[mt][nt][2];
                        stage[(r0+8)*33 + c0 + 1] = s8 - 2.0f*acc[mt][nt][3];
                    }
                }
            }
            __syncthreads();
            {
                float sqc = sq[col0 + cb + lane];
                #pragma unroll 4
                for (int rr = 0; rr < 16; rr++) {
                    int r = wid*16 + rr;
                    dst[(size_t)(row0 + r)*NP + col0 + cb + lane] = stage[r*33 + lane] + sqc;
                }
            }
            if (mirror) {
                #pragma unroll
                for (int q = 0; q < 4; q++) {
                    int cc = wid*4 + q;
                    float sqc = sq[col0 + cb + cc];
                    #pragma unroll
                    for (int it = 0; it < 4; it++) {
                        int r = it*32 + lane;
                        dst[(size_t)(col0 + cb + cc)*NP + row0 + r] = stage[r*33 + cc] + sqc;
                    }
                }
            }
            __syncthreads();
        }
    } else {
        int t = id - DIST_CTAS;
        int by = t / 6, bx = t - by*6;
        int row0 = by*128, col0 = bx*128;

        const __nv_bfloat16* srcs[4] = {d_xf_hi, d_xf_lo, d_wuv_hi, d_wuv_lo};
        int rbase[4] = {row0, row0, col0, col0};
        mma_mainloop<Cc>(srcs, rbase, sb, tid, lane, warp_m, warp_n, acc);

        #pragma unroll 1
        for (int g = 0; g < 4; g++) {
            int cb = g*32;
            if (warp_n == g) {
                #pragma unroll
                for (int mt = 0; mt < 4; mt++) {
                    int r0 = warp_m*64 + mt*16 + (lane >> 2);
                    #pragma unroll
                    for (int nt = 0; nt < 4; nt++) {
                        int c0 = nt*8 + (lane & 3)*2;
                        stage[r0*33 + c0]     = acc[mt][nt][0];
                        stage[r0*33 + c0 + 1] = acc[mt][nt][1];
                        stage[(r0+8)*33 + c0]     = acc[mt][nt][2];
                        stage[(r0+8)*33 + c0 + 1] = acc[mt][nt][3];
                    }
                }
            }
            __syncthreads();
            #pragma unroll 4
            for (int rr = 0; rr < 16; rr++) {
                int r = wid*16 + rr;
                d_Yt[(size_t)(row0 + r)*768 + col0 + cb + lane] = stage[r*33 + lane];
            }
            __syncthreads();
        }
    }
}

// ---------------- fused tail: M=128 tile, 512 threads (16 warps, 4x4) ----------------
// phase A: h = relu(g.W1^T + c1), kept split-bf16 in smem (ldmatrix chunk format)
// phase B: out = relu(h.W2^T + c2) + h, A from smem
__global__ void __launch_bounds__(512) mma_tail(float* __restrict__ outp)
{
    extern __shared__ char sm[];
    unsigned sb = smem_u32(sm);
    int tid = threadIdx.x, lane = tid & 31, wid = tid >> 5;   // wid 0..15
    int warp_m = wid & 3, warp_n = wid >> 2;                  // 4 x 4
    int row0 = blockIdx.x*128;

    float acc[2][4][4];
    float* stage = reinterpret_cast<float*>(sm);

    // ================= phase A: two 128-col passes, K=384 =================
    #pragma unroll 1
    for (int p = 0; p < 2; p++) {
        #pragma unroll
        for (int mt = 0; mt < 2; mt++)
            #pragma unroll
            for (int nt = 0; nt < 4; nt++)
                #pragma unroll
                for (int e = 0; e < 4; e++) acc[mt][nt][e] = 0.0f;

        int colbase = p*128;
        auto load_A = [&](int ch, int s) {
            unsigned so = sb + s*STAGE_B;
            int k0 = ch*BK;
            int row = tid >> 2, c4 = tid & 3;   // 512 threads = 128 rows x 4
            cpa16(so + row*TROW_B + c4*16,
                  d_g_hi + (size_t)(row0 + row)*384 + k0 + c4*8);
            cpa16(so + TILE_B + row*TROW_B + c4*16,
                  d_g_lo + (size_t)(row0 + row)*384 + k0 + c4*8);
            cpa16(so + 2*TILE_B + row*TROW_B + c4*16,
                  d_w1_hi + (size_t)(colbase + row)*384 + k0 + c4*8);
            cpa16(so + 3*TILE_B + row*TROW_B + c4*16,
                  d_w1_lo + (size_t)(colbase + row)*384 + k0 + c4*8);
        };

        load_A(0, 0);
        CP_COMMIT();

        #pragma unroll
        for (int ch = 0; ch < 12; ch++) {
            if (ch + 1 < 12) { load_A(ch+1, (ch+1)&1); CP_COMMIT(); CP_WAIT(1); }
            else             { CP_WAIT(0); }
            __syncthreads();

            unsigned so = sb + (ch&1)*STAGE_B;
            #pragma unroll
            for (int ks = 0; ks < 2; ks++) {
                unsigned ah[2][4], al[2][4], bh[4][2], bl[4][2];
                #pragma unroll
                for (int mt = 0; mt < 2; mt++) {
                    unsigned ra = so + (warp_m*32 + mt*16 + (lane & 15))*TROW_B
                                + ks*32 + (lane >> 4)*16;
                    ldm4(ah[mt], ra);
                    ldm4(al[mt], ra + TILE_B);
                }
                #pragma unroll
                for (int q = 0; q < 2; q++) {
                    int nrow = warp_n*32 + q*16 + (lane >> 4)*8 + (lane & 7);
                    unsigned rb = so + 2*TILE_B + nrow*TROW_B + ks*32 + ((lane >> 3) & 1)*16;
                    unsigned r4[4];
                    ldm4(r4, rb);
                    bh[2*q][0] = r4[0]; bh[2*q][1] = r4[1];
                    bh[2*q+1][0] = r4[2]; bh[2*q+1][1] = r4[3];
                    ldm4(r4, rb + TILE_B);
                    bl[2*q][0] = r4[0]; bl[2*q][1] = r4[1];
                    bl[2*q+1][0] = r4[2]; bl[2*q+1][1] = r4[3];
                }
                #pragma unroll
                for (int mt = 0; mt < 2; mt++)
                    #pragma unroll
                    for (int nt = 0; nt < 4; nt++) {
                        mma_bf16(acc[mt][nt], ah[mt], bh[nt]);
                        mma_bf16(acc[mt][nt], ah[mt], bl[nt]);
                        mma_bf16(acc[mt][nt], al[mt], bh[nt]);
                    }
            }
            __syncthreads();
        }

        // fragments -> persistent split-h smem tiles (ldmatrix A chunk format)
        #pragma unroll
        for (int mt = 0; mt < 2; mt++) {
            int r0 = warp_m*32 + mt*16 + (lane >> 2);
            #pragma unroll
            for (int nt = 0; nt < 4; nt++) {
                int c0 = warp_n*32 + nt*8 + (lane & 3)*2;
                #pragma unroll
                for (int e = 0; e < 4; e++) {
                    int r  = r0 + ((e >> 1) << 3);
                    int gc = colbase + c0 + (e & 1);
                    if (gc < Cc) {
                        float v = fmaxf(acc[mt][nt][e] + d_c1[gc], 0.0f);
                        __nv_bfloat16 hh = __float2bfloat16(v);
                        unsigned off = (unsigned)(gc >> 5)*TILE_B + r*TROW_B + (gc & 31)*2;
                        *reinterpret_cast<__nv_bfloat16*>(sm + OFF_A2H + off) = hh;
                        *reinterpret_cast<__nv_bfloat16*>(sm + OFF_A2L + off) =
                            __float2bfloat16(v - __bfloat162float(hh));
                    }
                }
            }
        }
        __syncthreads();
    }

    // ================= phase B: two 128-col passes, K=192, A from smem ==========
    #pragma unroll 1
    for (int p = 0; p < 2; p++) {
        #pragma unroll
        for (int mt = 0; mt < 2; mt++)
            #pragma unroll
            for (int nt = 0; nt < 4; nt++)
                #pragma unroll
                for (int e = 0; e < 4; e++) acc[mt][nt][e] = 0.0f;

        int colbase = p*128;
        auto load_B2 = [&](int ch, int s) {
            unsigned so = sb + s*B_STG2;
            int k0 = ch*BK;
            int row = tid >> 2, c4 = tid & 3;
            cpa16(so + row*TROW_B + c4*16,
                  d_w2_hi + (size_t)(colbase + row)*Cc + k0 + c4*8);
            cpa16(so + TILE_B + row*TROW_B + c4*16,
                  d_w2_lo + (size_t)(colbase + row)*Cc + k0 + c4*8);
        };

        load_B2(0, 0);
        CP_COMMIT();

        #pragma unroll
        for (int ch = 0; ch < 6; ch++) {
            if (ch + 1 < 6) { load_B2(ch+1, (ch+1)&1); CP_COMMIT(); CP_WAIT(1); }
            else            { CP_WAIT(0); }
            __syncthreads();

            unsigned sob = sb + (ch&1)*B_STG2;
            unsigned soa = sb + OFF_A2H + (unsigned)ch*TILE_B;
            #pragma unroll
            for (int ks = 0; ks < 2; ks++) {
                unsigned ah[2][4], al[2][4], bh[4][2], bl[4][2];
                #pragma unroll
                for (int mt = 0; mt < 2; mt++) {
                    unsigned ra = soa + (warp_m*32 + mt*16 + (lane & 15))*TROW_B
                                + ks*32 + (lane >> 4)*16;
                    ldm4(ah[mt], ra);
                    ldm4(al[mt], ra + 6*TILE_B);
                }
                #pragma unroll
                for (int q = 0; q < 2; q++) {
                    int nrow = warp_n*32 + q*16 + (lane >> 4)*8 + (lane & 7);
                    unsigned rb = sob + nrow*TROW_B + ks*32 + ((lane >> 3) & 1)*16;
                    unsigned r4[4];
                    ldm4(r4, rb);
                    bh[2*q][0] = r4[0]; bh[2*q][1] = r4[1];
                    bh[2*q+1][0] = r4[2]; bh[2*q+1][1] = r4[3];
                    ldm4(r4, rb + TILE_B);
                    bl[2*q][0] = r4[0]; bl[2*q][1] = r4[1];
                    bl[2*q+1][0] = r4[2]; bl[2*q+1][1] = r4[3];
                }
                #pragma unroll
                for (int mt = 0; mt < 2; mt++)
                    #pragma unroll
                    for (int nt = 0; nt < 4; nt++) {
                        mma_bf16(acc[mt][nt], ah[mt], bh[nt]);
                        mma_bf16(acc[mt][nt], ah[mt], bl[nt]);
                        mma_bf16(acc[mt][nt], al[mt], bh[nt]);
                    }
            }
            __syncthreads();
        }

        // epilogue: stage transpose, relu+c2, add shortcut from smem, scatter
        #pragma unroll 1
        for (int g = 0; g < 4; g++) {
            int cb = g*32;
            if (warp_n == g) {
                #pragma unroll
                for (int mt = 0; mt < 2; mt++) {
                    int r0 = warp_m*32 + mt*16 + (lane >> 2);
                    #pragma unroll
                    for (int nt = 0; nt < 4; nt++) {
                        int c0 = nt*8 + (lane & 3)*2;
                        stage[r0*33 + c0]     = acc[mt][nt][0];
                        stage[r0*33 + c0 + 1] = acc[mt][nt][1];
                        stage[(r0+8)*33 + c0]     = acc[mt][nt][2];
                        stage[(r0+8)*33 + c0 + 1] = acc[mt][nt][3];
                    }
                }
            }
            __syncthreads();
            #pragma unroll
            for (int q = 0; q < 2; q++) {
                int cc = wid*2 + q;
                int gc = colbase + cb + cc;
                if (gc < Cc) {
                    float c2v = d_c2[gc];
                    unsigned ob = (unsigned)(gc >> 5)*TILE_B + (gc & 31)*2;
                    #pragma unroll
                    for (int it = 0; it < 4; it++) {
                        int r = it*32 + lane;
                        int gr = row0 + r;
                        unsigned off = ob + r*TROW_B;
                        float sc = __bfloat162float(*reinterpret_cast<__nv_bfloat16*>(sm + OFF_A2H + off))
                                 + __bfloat162float(*reinterpret_cast<__nv_bfloat16*>(sm + OFF_A2L + off));
                        float v = fmaxf(stage[r*33 + cc] + c2v, 0.0f) + sc;
                        int b = gr / Nn, n = gr - b*Nn;
                        outp[((size_t)b*Cc + gc)*Nn + n] = v;
                    }
                }
            }
            __syncthreads();
        }
    }
}

// ---------------- fused top-9 + gather_max ----------------
__device__ __forceinline__ unsigned fkey32(float v) {
    unsigned u = __float_as_uint(v);
    return (u & 0x80000000u) ? ~u : (u | 0x80000000u);
}

#define TK_CAP 128

__global__ void __launch_bounds__(128) topk_gather(const float* __restrict__ be)
{
    __shared__ unsigned long long kb_s[4][TK_CAP];
    __shared__ int ids[4][KK];
    int lane = threadIdx.x & 31;
    int w    = threadIdx.x >> 5;
    int row  = blockIdx.x*4 + w;
    int b = row / Nn, n = row - b*Nn;
    const float* dr = d_dist + ((size_t)b*NP + n)*NP;
    unsigned long long* kb = kb_s[w];

    float mv = FLT_MAX;
    #pragma unroll
    for (int i = 0; i < 13; i++) {
        float4 v = reinterpret_cast<const float4*>(dr)[i*32 + lane];
        mv = fminf(mv, fminf(fminf(v.x, v.y), fminf(v.z, v.w)));
    }

    float tau = 0.0f;
    float mm = mv;
    #pragma unroll
    for (int r = 0; r < 9; r++) {
        float v = mm;
        #pragma unroll
        for (int off = 16; off; off >>= 1) v = fminf(v, __shfl_xor_sync(0xffffffffu, v, off));
        unsigned bl = __ballot_sync(0xffffffffu, mm == v);
        int src = __ffs(bl) - 1;
        if (lane == src) mm = FLT_MAX;
        tau = v;
    }

    int cnt = 0;
    #pragma unroll 1
    for (int i = 0; i < 13; i++) {
        float4 v = reinterpret_cast<const float4*>(dr)[i*32 + lane];
        int mbase = (i*32 + lane)*4;
        float vv[4] = {v.x, v.y, v.z, v.w};
        #pragma unroll
        for (int c = 0; c < 4; c++) {
            bool pr = (vv[c] <= tau);
            unsigned msk = __ballot_sync(0xffffffffu, pr);
            if (pr) {
                int pos = cnt + __popc(msk & ((1u << lane) - 1u));
                if (pos < TK_CAP)
                    kb[pos] = ((unsigned long long)fkey32(vv[c]) << 32) | (unsigned)(mbase + c);
            }
            cnt += __popc(msk);
        }
    }

    if (cnt <= TK_CAP) {
        #pragma unroll 1
        for (int r = 0; r < 9; r++) {
            unsigned long long best = ~0ULL;
            #pragma unroll
            for (int s = 0; s < 4; s++) {
                int pp = lane + s*32;
                if (pp < cnt) { unsigned long long k = kb[pp]; if (k < best) best = k; }
            }
            #pragma unroll
            for (int off = 16; off; off >>= 1) {
                unsigned long long o = __shfl_xor_sync(0xffffffffu, best, off);
                if (o < best) best = o;
            }
            #pragma unroll
            for (int s = 0; s < 4; s++) {
                int pp = lane + s*32;
                if (pp < cnt && kb[pp] == best) kb[pp] = ~0ULL;
            }
            if (lane == 0) ids[w][r] = (int)(best & 0xffffffffu);
        }
    } else if (lane == 0) {
        unsigned long long bd[9];
        #pragma unroll
        for (int s = 0; s < 9; s++) bd[s] = ~0ULL;
        unsigned long long wk = ~0ULL; int ws = 0;
        for (int m2 = 0; m2 < NP; m2++) {
            unsigned long long k = ((unsigned long long)fkey32(dr[m2]) << 32) | (unsigned)m2;
            if (k < wk) {
                bd[ws] = k;
                wk = bd[0]; ws = 0;
                #pragma unroll
                for (int s = 1; s < 9; s++) if (bd[s] > wk) { wk = bd[s]; ws = s; }
            }
        }
        #pragma unroll
        for (int s = 0; s < 9; s++) ids[w][s] = (int)(bd[s] & 0xffffffffu);
    }

    __syncthreads();

    int tid = threadIdx.x;
    #pragma unroll 1
    for (int rw = 0; rw < 4; rw++) {
        int j = blockIdx.x*4 + rw;
        int bb = j / Nn;
        int base = bb*Nn;
        int id2[9];
        #pragma unroll
        for (int k = 0; k < 9; k++) id2[k] = ids[rw][k];
        #pragma unroll
        for (int it = 0; it < 3; it++) {
            int o = it*128 + tid;
            float m = -FLT_MAX;
            #pragma unroll
            for (int k = 0; k < 9; k++)
                m = fmaxf(m, d_Yt[(size_t)(base + id2[k])*768 + 384 + o]);
            float u = d_Yt[(size_t)j*768 + o] + be[o];
            float v = fmaxf(u + m, 0.0f);
            split_store(v, d_g_hi, d_g_lo, (size_t)j*384 + o);
        }
    }
}

// ---------------- launch ----------------
extern "C" void kernel_launch(void* const* d_in, const int* in_sizes, int n_in,
                              void* d_out, int out_size)
{
    const float* x   = (const float*)d_in[0];
    const float* pos = (const float*)d_in[1];
    const float* We  = (const float*)d_in[2];
    const float* be  = (const float*)d_in[3];
    const float* W1  = (const float*)d_in[4];
    const float* b1  = (const float*)d_in[5];
    const float* g1  = (const float*)d_in[6];
    const float* bb1 = (const float*)d_in[7];
    const float* W2  = (const float*)d_in[8];
    const float* b2  = (const float*)d_in[9];
    const float* g2  = (const float*)d_in[10];
    const float* bb2 = (const float*)d_in[11];
    float* out = (float*)d_out;

    cudaFuncSetAttribute(phase1,   cudaFuncAttributeMaxDynamicSharedMemorySize, GSMEM);
    cudaFuncSetAttribute(mma_tail, cudaFuncAttributeMaxDynamicSharedMemorySize, SM_TAIL);

    prep_all<<<BNN + 768 + Bz*(NP-Nn), 192>>>(x, pos, We, W1, b1, g1, bb1, W2, b2, g2, bb2);
    phase1<<<DIST_CTAS + G1_CTAS, 256, GSMEM>>>();
    topk_gather<<<BNN/4, 128>>>(be);
    mma_tail<<<BNN/128, 512, SM_TAIL>>>(out);
}

// round 14
// speedup vs baseline: 1.1432x; 1.0571x over previous
#include <cuda_runtime.h>
#include <cuda_bf16.h>
#include <math.h>
#include <float.h>

#define Bz 8
#define Cc 192
#define Nn 1568
#define NP 1664            /* 13*128 */
#define BNN (Bz*Nn)        /* 12544 = 98*128 */
#define KK 9
#define NBLK 13
#define NPAIR (NBLK*(NBLK+1)/2)     /* 91 */
#define DIST_CTAS (NPAIR*Bz)        /* 728 */
#define G1_CTAS (6*98)              /* 588 */

// smem tile geometry (128-row tiles)
#define BK 32
#define TROW_B 80                /* bytes per smem row: 40 bf16 (32 + 8 pad) */
#define TILE_B (128*TROW_B)      /* 10240 */
#define STAGE_B (4*TILE_B)       /* phase1 stage */
#define GSMEM (2*STAGE_B)        /* 81920 */

// ---- fused tail (single-pass N=192, 512 threads) ----
#define BTILE_B (192*TROW_B)              /* 15360 */
#define STG_TA  (2*TILE_B + 2*BTILE_B)    /* 51200: gh, gl, w1h, w1l */
#define OFF_H2  (2*STG_TA)                /* 102400 */
#define OFF_L2  (OFF_H2 + 6*TILE_B)       /* 163840 */
#define SM_TAIL2 (OFF_L2 + 6*TILE_B)      /* 225280 */
#define STG_TB  (2*BTILE_B)               /* 30720 */

// ---------------- scratch (static device globals; no allocation) ----------------
__device__ __align__(256) __nv_bfloat16 d_xn_hi[(size_t)Bz*NP*Cc], d_xn_lo[(size_t)Bz*NP*Cc];
__device__ __align__(256) __nv_bfloat16 d_xf_hi[(size_t)BNN*Cc],   d_xf_lo[(size_t)BNN*Cc];
__device__ __align__(256) float d_sqp[Bz*NP];
__device__ __align__(256) float d_dist[(size_t)Bz*NP*NP];
__device__ __align__(256) __nv_bfloat16 d_wuv_hi[768*Cc], d_wuv_lo[768*Cc];
__device__ __align__(256) __nv_bfloat16 d_w1_hi[256*384], d_w1_lo[256*384];
__device__ __align__(256) __nv_bfloat16 d_w2_hi[256*Cc],  d_w2_lo[256*Cc];
__device__ __align__(256) float d_c1[Cc], d_c2[Cc];
__device__ __align__(256) float d_Yt[(size_t)BNN*768];
__device__ __align__(256) __nv_bfloat16 d_g_hi[(size_t)BNN*384], d_g_lo[(size_t)BNN*384];

// ---------------- PTX helpers ----------------
__device__ __forceinline__ unsigned smem_u32(const void* p) {
    unsigned a;
    asm("{ .reg .u64 t; cvta.to.shared.u64 t, %1; cvt.u32.u64 %0, t; }" : "=r"(a) : "l"(p));
    return a;
}
__device__ __forceinline__ void cpa16(unsigned s, const void* g) {
    asm volatile("cp.async.cg.shared.global [%0], [%1], 16;" :: "r"(s), "l"(g));
}
#define CP_COMMIT() asm volatile("cp.async.commit_group;" ::: "memory")
#define CP_WAIT(n)  asm volatile("cp.async.wait_group %0;" :: "n"(n) : "memory")

__device__ __forceinline__ void ldm4(unsigned* r, unsigned a) {
    asm volatile("ldmatrix.sync.aligned.m8n8.x4.shared.b16 {%0,%1,%2,%3}, [%4];"
        : "=r"(r[0]), "=r"(r[1]), "=r"(r[2]), "=r"(r[3]) : "r"(a));
}
__device__ __forceinline__ void mma_bf16(float* c, const unsigned* a, const unsigned* b) {
    asm volatile("mma.sync.aligned.m16n8k16.row.col.f32.bf16.bf16.f32 "
        "{%0,%1,%2,%3}, {%4,%5,%6,%7}, {%8,%9}, {%0,%1,%2,%3};"
        : "+f"(c[0]), "+f"(c[1]), "+f"(c[2]), "+f"(c[3])
        : "r"(a[0]), "r"(a[1]), "r"(a[2]), "r"(a[3]), "r"(b[0]), "r"(b[1]));
}

__device__ __forceinline__ void split_store(float v, __nv_bfloat16* hi, __nv_bfloat16* lo, size_t i) {
    __nv_bfloat16 h = __float2bfloat16(v);
    hi[i] = h;
    lo[i] = __float2bfloat16(v - __bfloat162float(h));
}

// ---------------- fused prep (R10 proven version): xf | weights | pad ----------------
__global__ void prep_all(const float* __restrict__ x, const float* __restrict__ pos,
                         const float* __restrict__ We, const float* __restrict__ W1,
                         const float* __restrict__ b1, const float* __restrict__ g1,
                         const float* __restrict__ bb1, const float* __restrict__ W2,
                         const float* __restrict__ b2, const float* __restrict__ g2,
                         const float* __restrict__ bb2)
{
    int blk = blockIdx.x;
    int c = threadIdx.x;              // 192 threads
    if (blk < BNN) {
        int j = blk;
        int b = j / Nn, n = j - b*Nn;
        float v = x[((size_t)b*Cc + c)*Nn + n] + pos[n*Cc + c];
        split_store(v, d_xf_hi, d_xf_lo, (size_t)j*Cc + c);

        __shared__ float red[Cc];
        __shared__ float s_nrm;
        red[c] = v*v;
        __syncthreads();
        if (c < 64) red[c] += red[c+64] + red[c+128];
        __syncthreads();
        if (c < 32) {
            float s = red[c] + red[c+32];
            #pragma unroll
            for (int o = 16; o; o >>= 1) s += __shfl_xor_sync(0xffffffffu, s, o);
            if (c == 0) s_nrm = fmaxf(sqrtf(s), 1e-12f);
        }
        __syncthreads();
        float xn = v / s_nrm;
        split_store(xn, d_xn_hi, d_xn_lo, ((size_t)b*NP + n)*Cc + c);

        red[c] = xn*xn;
        __syncthreads();
        if (c < 64) red[c] += red[c+64] + red[c+128];
        __syncthreads();
        if (c < 32) {
            float s = red[c] + red[c+32];
            #pragma unroll
            for (int o = 16; o; o >>= 1) s += __shfl_xor_sync(0xffffffffu, s, o);
            if (c == 0) d_sqp[b*NP + n] = s;
        }
    } else if (blk < BNN + 768) {
        int i = (blk - BNN)*192 + c;
        const float denom = (float)sqrt(1.0 + 1e-5);
        if (i < 768*Cc) {
            int o = i/Cc, cc = i - o*Cc;
            float v = (o < 384) ? (We[o*384 + cc] - We[o*384 + 192 + cc])
                                : We[(o-384)*384 + 192 + cc];
            split_store(v, d_wuv_hi, d_wuv_lo, i);
        }
        if (i < 256*384) {
            int o = i/384;
            float v = (o < 192) ? W1[i] * (g1[o]/denom) : 0.0f;
            split_store(v, d_w1_hi, d_w1_lo, i);
        }
        if (i < 256*192) {
            int o = i/192;
            float v = (o < 192) ? W2[i] * (g2[o]/denom) : 0.0f;
            split_store(v, d_w2_hi, d_w2_lo, i);
        }
        if (i < Cc) {
            d_c1[i] = b1[i]*(g1[i]/denom) + bb1[i];
            d_c2[i] = b2[i]*(g2[i]/denom) + bb2[i];
        }
    } else {
        int r = blk - BNN - 768;
        int b = r / (NP-Nn), pr = r - b*(NP-Nn);
        int row = Nn + pr;
        size_t i = ((size_t)b*NP + row)*Cc + c;
        d_xn_hi[i] = __float2bfloat16(0.0f);
        d_xn_lo[i] = __float2bfloat16(0.0f);
        if (c == 0) d_sqp[b*NP + row] = 1e30f;
    }
}

// ============ shared 128x128 mainloop, 256 threads (phase1) ============
template<int KDIM>
__device__ __forceinline__ void mma_mainloop(
    const __nv_bfloat16* const* srcs, const int* rbase,
    unsigned sb, int tid, int lane, int warp_m, int warp_n,
    float acc[4][4][4])
{
    constexpr int NCH = KDIM / BK;
    auto load_chunk = [&](int ch, int s) {
        unsigned so = sb + s*STAGE_B;
        int k0 = ch*BK;
        #pragma unroll
        for (int t = 0; t < 4; t++) {
            #pragma unroll
            for (int q = 0; q < 2; q++) {
                int v = tid + q*256;
                int row = v >> 2, c4 = v & 3;
                cpa16(so + t*TILE_B + row*TROW_B + c4*16,
                      srcs[t] + (size_t)(rbase[t] + row)*KDIM + k0 + c4*8);
            }
        }
    };

    load_chunk(0, 0);
    CP_COMMIT();

    #pragma unroll
    for (int ch = 0; ch < NCH; ch++) {
        if (ch + 1 < NCH) { load_chunk(ch+1, (ch+1)&1); CP_COMMIT(); CP_WAIT(1); }
        else              { CP_WAIT(0); }
        __syncthreads();

        unsigned so = sb + (ch&1)*STAGE_B;
        #pragma unroll
        for (int ks = 0; ks < 2; ks++) {
            unsigned ah[4][4], al[4][4], bh[4][2], bl[4][2];
            #pragma unroll
            for (int mt = 0; mt < 4; mt++) {
                unsigned ra = so + (warp_m*64 + mt*16 + (lane & 15))*TROW_B
                            + ks*32 + (lane >> 4)*16;
                ldm4(ah[mt], ra);
                ldm4(al[mt], ra + TILE_B);
            }
            #pragma unroll
            for (int p = 0; p < 2; p++) {
                int nrow = warp_n*32 + p*16 + (lane >> 4)*8 + (lane & 7);
                unsigned rb = so + 2*TILE_B + nrow*TROW_B + ks*32 + ((lane >> 3) & 1)*16;
                unsigned r4[4];
                ldm4(r4, rb);
                bh[2*p][0] = r4[0]; bh[2*p][1] = r4[1];
                bh[2*p+1][0] = r4[2]; bh[2*p+1][1] = r4[3];
                ldm4(r4, rb + TILE_B);
                bl[2*p][0] = r4[0]; bl[2*p][1] = r4[1];
                bl[2*p+1][0] = r4[2]; bl[2*p+1][1] = r4[3];
            }
            #pragma unroll
            for (int mt = 0; mt < 4; mt++)
                #pragma unroll
                for (int nt = 0; nt < 4; nt++) {
                    mma_bf16(acc[mt][nt], ah[mt], bh[nt]);
                    mma_bf16(acc[mt][nt], ah[mt], bl[nt]);
                    mma_bf16(acc[mt][nt], al[mt], bh[nt]);
                }
        }
        __syncthreads();
    }
}

// ---------------- phase1: dist (symmetric) + gemm1 (Yt) in ONE launch ----------------
__global__ void __launch_bounds__(256, 2) phase1()
{
    extern __shared__ char sm[];
    unsigned sb = smem_u32(sm);
    int tid = threadIdx.x, lane = tid & 31, wid = tid >> 5;
    int warp_m = wid & 1, warp_n = wid >> 1;
    int id = blockIdx.x;

    float acc[4][4][4];
    #pragma unroll
    for (int mt = 0; mt < 4; mt++)
        #pragma unroll
        for (int nt = 0; nt < 4; nt++)
            #pragma unroll
            for (int e = 0; e < 4; e++) acc[mt][nt][e] = 0.0f;

    float* stage = reinterpret_cast<float*>(sm);   // 128 x 33 floats

    if (id < DIST_CTAS) {
        int z = id / NPAIR;
        int p = id - z*NPAIR, by = 0;
        while (p >= NBLK - by) { p -= NBLK - by; by++; }
        int bx = by + p;
        int row0 = by*128, col0 = bx*128;

        size_t zo = (size_t)z*NP*Cc;
        const __nv_bfloat16* srcs[4] = {d_xn_hi + zo, d_xn_lo + zo, d_xn_hi + zo, d_xn_lo + zo};
        int rbase[4] = {row0, row0, col0, col0};
        mma_mainloop<Cc>(srcs, rbase, sb, tid, lane, warp_m, warp_n, acc);

        const float* sq = d_sqp + z*NP;
        float* dst = d_dist + (size_t)z*NP*NP;
        bool mirror = (bx != by);

        #pragma unroll 1
        for (int g = 0; g < 4; g++) {
            int cb = g*32;
            if (warp_n == g) {
                #pragma unroll
                for (int mt = 0; mt < 4; mt++) {
                    int r0 = warp_m*64 + mt*16 + (lane >> 2);
                    float s0 = sq[row0 + r0];
                    float s8 = sq[row0 + r0 + 8];
                    #pragma unroll
                    for (int nt = 0; nt < 4; nt++) {
                        int c0 = nt*8 + (lane & 3)*2;
                        stage[r0*33 + c0]     = s0 - 2.0f*acc[mt][nt][0];
                        stage[r0*33 + c0 + 1] = s0 - 2.0f*acc[mt][nt][1];
                        stage[(r0+8)*33 + c0]     = s8 - 2.0f*acc[mt][nt][2];
                        stage[(r0+8)*33 + c0 + 1] = s8 - 2.0f*acc[mt][nt][3];
                    }
                }
            }
            __syncthreads();
            {
                float sqc = sq[col0 + cb + lane];
                #pragma unroll 4
                for (int rr = 0; rr < 16; rr++) {
                    int r = wid*16 + rr;
                    dst[(size_t)(row0 + r)*NP + col0 + cb + lane] = stage[r*33 + lane] + sqc;
                }
            }
            if (mirror) {
                #pragma unroll
                for (int q = 0; q < 4; q++) {
                    int cc = wid*4 + q;
                    float sqc = sq[col0 + cb + cc];
                    #pragma unroll
                    for (int it = 0; it < 4; it++) {
                        int r = it*32 + lane;
                        dst[(size_t)(col0 + cb + cc)*NP + row0 + r] = stage[r*33 + cc] + sqc;
                    }
                }
            }
            __syncthreads();
        }
    } else {
        int t = id - DIST_CTAS;
        int by = t / 6, bx = t - by*6;
        int row0 = by*128, col0 = bx*128;

        const __nv_bfloat16* srcs[4] = {d_xf_hi, d_xf_lo, d_wuv_hi, d_wuv_lo};
        int rbase[4] = {row0, row0, col0, col0};
        mma_mainloop<Cc>(srcs, rbase, sb, tid, lane, warp_m, warp_n, acc);

        #pragma unroll 1
        for (int g = 0; g < 4; g++) {
            int cb = g*32;
            if (warp_n == g) {
                #pragma unroll
                for (int mt = 0; mt < 4; mt++) {
                    int r0 = warp_m*64 + mt*16 + (lane >> 2);
                    #pragma unroll
                    for (int nt = 0; nt < 4; nt++) {
                        int c0 = nt*8 + (lane & 3)*2;
                        stage[r0*33 + c0]     = acc[mt][nt][0];
                        stage[r0*33 + c0 + 1] = acc[mt][nt][1];
                        stage[(r0+8)*33 + c0]     = acc[mt][nt][2];
                        stage[(r0+8)*33 + c0 + 1] = acc[mt][nt][3];
                    }
                }
            }
            __syncthreads();
            #pragma unroll 4
            for (int rr = 0; rr < 16; rr++) {
                int r = wid*16 + rr;
                d_Yt[(size_t)(row0 + r)*768 + col0 + cb + lane] = stage[r*33 + lane];
            }
            __syncthreads();
        }
    }
}

// ---------------- fused tail: M=128, N=192 single pass, 512 threads ----------------
__global__ void __launch_bounds__(512) mma_tail(float* __restrict__ outp)
{
    extern __shared__ char sm[];
    unsigned sb = smem_u32(sm);
    int tid = threadIdx.x, lane = tid & 31, wid = tid >> 5;   // 16 warps
    int warp_m = wid & 3, warp_n = wid >> 2;                  // 4 x 4; warp = 32 rows x 48 cols
    int row0 = blockIdx.x*128;

    float acc[2][6][4];

    // ================= phase A: h = relu(g.W1^T + c1), K=384, single N pass =========
    #pragma unroll
    for (int mt = 0; mt < 2; mt++)
        #pragma unroll
        for (int nt = 0; nt < 6; nt++)
            #pragma unroll
            for (int e = 0; e < 4; e++) acc[mt][nt][e] = 0.0f;

    auto load_A = [&](int ch, int s) {
        unsigned so = sb + s*STG_TA;
        int k0 = ch*BK;
        int row = tid >> 2, c4 = tid & 3;   // 512 = 128 rows x 4
        cpa16(so + row*TROW_B + c4*16,
              d_g_hi + (size_t)(row0 + row)*384 + k0 + c4*8);
        cpa16(so + TILE_B + row*TROW_B + c4*16,
              d_g_lo + (size_t)(row0 + row)*384 + k0 + c4*8);
        #pragma unroll
        for (int q = 0; q < 2; q++) {
            int v = tid + q*512;
            if (v < 768) {                   // 192 rows x 4
                int r2 = v >> 2, c2 = v & 3;
                cpa16(so + 2*TILE_B + r2*TROW_B + c2*16,
                      d_w1_hi + (size_t)r2*384 + k0 + c2*8);
                cpa16(so + 2*TILE_B + BTILE_B + r2*TROW_B + c2*16,
                      d_w1_lo + (size_t)r2*384 + k0 + c2*8);
            }
        }
    };

    load_A(0, 0);
    CP_COMMIT();

    #pragma unroll
    for (int ch = 0; ch < 12; ch++) {
        if (ch + 1 < 12) { load_A(ch+1, (ch+1)&1); CP_COMMIT(); CP_WAIT(1); }
        else             { CP_WAIT(0); }
        __syncthreads();

        unsigned so = sb + (ch&1)*STG_TA;
        #pragma unroll
        for (int ks = 0; ks < 2; ks++) {
            unsigned ah[2][4], al[2][4], bh[6][2], bl[6][2];
            #pragma unroll
            for (int mt = 0; mt < 2; mt++) {
                unsigned ra = so + (warp_m*32 + mt*16 + (lane & 15))*TROW_B
                            + ks*32 + (lane >> 4)*16;
                ldm4(ah[mt], ra);
                ldm4(al[mt], ra + TILE_B);
            }
            #pragma unroll
            for (int q = 0; q < 3; q++) {
                int nrow = warp_n*48 + q*16 + (lane >> 4)*8 + (lane & 7);
                unsigned rb = so + 2*TILE_B + nrow*TROW_B + ks*32 + ((lane >> 3) & 1)*16;
                unsigned r4[4];
                ldm4(r4, rb);
                bh[2*q][0] = r4[0]; bh[2*q][1] = r4[1];
                bh[2*q+1][0] = r4[2]; bh[2*q+1][1] = r4[3];
                ldm4(r4, rb + BTILE_B);
                bl[2*q][0] = r4[0]; bl[2*q][1] = r4[1];
                bl[2*q+1][0] = r4[2]; bl[2*q+1][1] = r4[3];
            }
            #pragma unroll
            for (int mt = 0; mt < 2; mt++)
                #pragma unroll
                for (int nt = 0; nt < 6; nt++) {
                    mma_bf16(acc[mt][nt], ah[mt], bh[nt]);
                    mma_bf16(acc[mt][nt], ah[mt], bl[nt]);
                    mma_bf16(acc[mt][nt], al[mt], bh[nt]);
                }
        }
        __syncthreads();
    }

    // fragments -> persistent split-h smem tiles (ldmatrix A chunk format)
    #pragma unroll
    for (int mt = 0; mt < 2; mt++) {
        int r0 = warp_m*32 + mt*16 + (lane >> 2);
        #pragma unroll
        for (int nt = 0; nt < 6; nt++) {
            int c0 = warp_n*48 + nt*8 + (lane & 3)*2;
            #pragma unroll
            for (int e = 0; e < 4; e++) {
                int r  = r0 + ((e >> 1) << 3);
                int gc = c0 + (e & 1);
                float v = fmaxf(acc[mt][nt][e] + d_c1[gc], 0.0f);
                __nv_bfloat16 hh = __float2bfloat16(v);
                unsigned off = (unsigned)(gc >> 5)*TILE_B + r*TROW_B + (gc & 31)*2;
                *reinterpret_cast<__nv_bfloat16*>(sm + OFF_H2 + off) = hh;
                *reinterpret_cast<__nv_bfloat16*>(sm + OFF_L2 + off) =
                    __float2bfloat16(v - __bfloat162float(hh));
            }
        }
    }
    __syncthreads();

    // ================= phase B: out = relu(h.W2^T + c2) + h, K=192, single N pass ====
    #pragma unroll
    for (int mt = 0; mt < 2; mt++)
        #pragma unroll
        for (int nt = 0; nt < 6; nt++)
            #pragma unroll
            for (int e = 0; e < 4; e++) acc[mt][nt][e] = 0.0f;

    auto load_B = [&](int ch, int s) {
        unsigned so = sb + s*STG_TB;
        int k0 = ch*BK;
        #pragma unroll
        for (int q = 0; q < 2; q++) {
            int v = tid + q*512;
            if (v < 768) {
                int r2 = v >> 2, c2 = v & 3;
                cpa16(so + r2*TROW_B + c2*16,
                      d_w2_hi + (size_t)r2*Cc + k0 + c2*8);
                cpa16(so + BTILE_B + r2*TROW_B + c2*16,
                      d_w2_lo + (size_t)r2*Cc + k0 + c2*8);
            }
        }
    };

    load_B(0, 0);
    CP_COMMIT();

    #pragma unroll
    for (int ch = 0; ch < 6; ch++) {
        if (ch + 1 < 6) { load_B(ch+1, (ch+1)&1); CP_COMMIT(); CP_WAIT(1); }
        else            { CP_WAIT(0); }
        __syncthreads();

        unsigned sob = sb + (ch&1)*STG_TB;
        unsigned soa = sb + OFF_H2 + (unsigned)ch*TILE_B;
        #pragma unroll
        for (int ks = 0; ks < 2; ks++) {
            unsigned ah[2][4], al[2][4], bh[6][2], bl[6][2];
            #pragma unroll
            for (int mt = 0; mt < 2; mt++) {
                unsigned ra = soa + (warp_m*32 + mt*16 + (lane & 15))*TROW_B
                            + ks*32 + (lane >> 4)*16;
                ldm4(ah[mt], ra);
                ldm4(al[mt], ra + 6*TILE_B);
            }
            #pragma unroll
            for (int q = 0; q < 3; q++) {
                int nrow = warp_n*48 + q*16 + (lane >> 4)*8 + (lane & 7);
                unsigned rb = sob + nrow*TROW_B + ks*32 + ((lane >> 3) & 1)*16;
                unsigned r4[4];
                ldm4(r4, rb);
                bh[2*q][0] = r4[0]; bh[2*q][1] = r4[1];
                bh[2*q+1][0] = r4[2]; bh[2*q+1][1] = r4[3];
                ldm4(r4, rb + BTILE_B);
                bl[2*q][0] = r4[0]; bl[2*q][1] = r4[1];
                bl[2*q+1][0] = r4[2]; bl[2*q+1][1] = r4[3];
            }
            #pragma unroll
            for (int mt = 0; mt < 2; mt++)
                #pragma unroll
                for (int nt = 0; nt < 6; nt++) {
                    mma_bf16(acc[mt][nt], ah[mt], bh[nt]);
                    mma_bf16(acc[mt][nt], ah[mt], bl[nt]);
                    mma_bf16(acc[mt][nt], al[mt], bh[nt]);
                }
        }
        __syncthreads();
    }

    // epilogue: full 128x193 stage transpose, then coalesced scatter
    float* stage = reinterpret_cast<float*>(sm);   // 128 x 193 floats (98816 B < OFF_H2)
    #pragma unroll
    for (int mt = 0; mt < 2; mt++) {
        int r0 = warp_m*32 + mt*16 + (lane >> 2);
        #pragma unroll
        for (int nt = 0; nt < 6; nt++) {
            int c0 = warp_n*48 + nt*8 + (lane & 3)*2;
            stage[r0*193 + c0]     = acc[mt][nt][0];
            stage[r0*193 + c0 + 1] = acc[mt][nt][1];
            stage[(r0+8)*193 + c0]     = acc[mt][nt][2];
            stage[(r0+8)*193 + c0 + 1] = acc[mt][nt][3];
        }
    }
    __syncthreads();

    #pragma unroll 2
    for (int i = 0; i < 48; i++) {
        int idx = i*512 + tid;
        int gc = idx >> 7, r = idx & 127;
        int gr = row0 + r;
        unsigned off = (unsigned)(gc >> 5)*TILE_B + r*TROW_B + (gc & 31)*2;
        float sc = __bfloat162float(*reinterpret_cast<__nv_bfloat16*>(sm + OFF_H2 + off))
                 + __bfloat162float(*reinterpret_cast<__nv_bfloat16*>(sm + OFF_L2 + off));
        float v = fmaxf(stage[r*193 + gc] + d_c2[gc], 0.0f) + sc;
        int b = gr / Nn, n = gr - b*Nn;
        outp[((size_t)b*Cc + gc)*Nn + n] = v;
    }
}

// ---------------- fused top-9 + gather_max ----------------
__device__ __forceinline__ unsigned fkey32(float v) {
    unsigned u = __float_as_uint(v);
    return (u & 0x80000000u) ? ~u : (u | 0x80000000u);
}

#define TK_CAP 128

__global__ void __launch_bounds__(128) topk_gather(const float* __restrict__ be)
{
    __shared__ unsigned long long kb_s[4][TK_CAP];
    __shared__ int ids[4][KK];
    int lane = threadIdx.x & 31;
    int w    = threadIdx.x >> 5;
    int row  = blockIdx.x*4 + w;
    int b = row / Nn, n = row - b*Nn;
    const float* dr = d_dist + ((size_t)b*NP + n)*NP;
    unsigned long long* kb = kb_s[w];

    float mv = FLT_MAX;
    #pragma unroll
    for (int i = 0; i < 13; i++) {
        float4 v = reinterpret_cast<const float4*>(dr)[i*32 + lane];
        mv = fminf(mv, fminf(fminf(v.x, v.y), fminf(v.z, v.w)));
    }

    float tau = 0.0f;
    float mm = mv;
    #pragma unroll
    for (int r = 0; r < 9; r++) {
        float v = mm;
        #pragma unroll
        for (int off = 16; off; off >>= 1) v = fminf(v, __shfl_xor_sync(0xffffffffu, v, off));
        unsigned bl = __ballot_sync(0xffffffffu, mm == v);
        int src = __ffs(bl) - 1;
        if (lane == src) mm = FLT_MAX;
        tau = v;
    }

    int cnt = 0;
    #pragma unroll 1
    for (int i = 0; i < 13; i++) {
        float4 v = reinterpret_cast<const float4*>(dr)[i*32 + lane];
        int mbase = (i*32 + lane)*4;
        float vv[4] = {v.x, v.y, v.z, v.w};
        #pragma unroll
        for (int c = 0; c < 4; c++) {
            bool pr = (vv[c] <= tau);
            unsigned msk = __ballot_sync(0xffffffffu, pr);
            if (pr) {
                int pos = cnt + __popc(msk & ((1u << lane) - 1u));
                if (pos < TK_CAP)
                    kb[pos] = ((unsigned long long)fkey32(vv[c]) << 32) | (unsigned)(mbase + c);
            }
            cnt += __popc(msk);
        }
    }

    if (cnt <= TK_CAP) {
        #pragma unroll 1
        for (int r = 0; r < 9; r++) {
            unsigned long long best = ~0ULL;
            #pragma unroll
            for (int s = 0; s < 4; s++) {
                int pp = lane + s*32;
                if (pp < cnt) { unsigned long long k = kb[pp]; if (k < best) best = k; }
            }
            #pragma unroll
            for (int off = 16; off; off >>= 1) {
                unsigned long long o = __shfl_xor_sync(0xffffffffu, best, off);
                if (o < best) best = o;
            }
            #pragma unroll
            for (int s = 0; s < 4; s++) {
                int pp = lane + s*32;
                if (pp < cnt && kb[pp] == best) kb[pp] = ~0ULL;
            }
            if (lane == 0) ids[w][r] = (int)(best & 0xffffffffu);
        }
    } else if (lane == 0) {
        unsigned long long bd[9];
        #pragma unroll
        for (int s = 0; s < 9; s++) bd[s] = ~0ULL;
        unsigned long long wk = ~0ULL; int ws = 0;
        for (int m2 = 0; m2 < NP; m2++) {
            unsigned long long k = ((unsigned long long)fkey32(dr[m2]) << 32) | (unsigned)m2;
            if (k < wk) {
                bd[ws] = k;
                wk = bd[0]; ws = 0;
                #pragma unroll
                for (int s = 1; s < 9; s++) if (bd[s] > wk) { wk = bd[s]; ws = s; }
            }
        }
        #pragma unroll
        for (int s = 0; s < 9; s++) ids[w][s] = (int)(bd[s] & 0xffffffffu);
    }

    __syncthreads();

    int tid = threadIdx.x;
    #pragma unroll 1
    for (int rw = 0; rw < 4; rw++) {
        int j = blockIdx.x*4 + rw;
        int bb = j / Nn;
        int base = bb*Nn;
        int id2[9];
        #pragma unroll
        for (int k = 0; k < 9; k++) id2[k] = ids[rw][k];
        #pragma unroll
        for (int it = 0; it < 3; it++) {
            int o = it*128 + tid;
            float m = -FLT_MAX;
            #pragma unroll
            for (int k = 0; k < 9; k++)
                m = fmaxf(m, d_Yt[(size_t)(base + id2[k])*768 + 384 + o]);
            float u = d_Yt[(size_t)j*768 + o] + be[o];
            float v = fmaxf(u + m, 0.0f);
            split_store(v, d_g_hi, d_g_lo, (size_t)j*384 + o);
        }
    }
}

// ---------------- launch ----------------
extern "C" void kernel_launch(void* const* d_in, const int* in_sizes, int n_in,
                              void* d_out, int out_size)
{
    const float* x   = (const float*)d_in[0];
    const float* pos = (const float*)d_in[1];
    const float* We  = (const float*)d_in[2];
    const float* be  = (const float*)d_in[3];
    const float* W1  = (const float*)d_in[4];
    const float* b1  = (const float*)d_in[5];
    const float* g1  = (const float*)d_in[6];
    const float* bb1 = (const float*)d_in[7];
    const float* W2  = (const float*)d_in[8];
    const float* b2  = (const float*)d_in[9];
    const float* g2  = (const float*)d_in[10];
    const float* bb2 = (const float*)d_in[11];
    float* out = (float*)d_out;

    cudaFuncSetAttribute(phase1,   cudaFuncAttributeMaxDynamicSharedMemorySize, GSMEM);
    cudaFuncSetAttribute(mma_tail, cudaFuncAttributeMaxDynamicSharedMemorySize, SM_TAIL2);

    prep_all<<<BNN + 768 + Bz*(NP-Nn), 192>>>(x, pos, We, W1, b1, g1, bb1, W2, b2, g2, bb2);
    phase1<<<DIST_CTAS + G1_CTAS, 256, GSMEM>>>();
    topk_gather<<<BNN/4, 128>>>(be);
    mma_tail<<<BNN/128, 512, SM_TAIL2>>>(out);
}

// round 15
// speedup vs baseline: 1.1535x; 1.0090x over previous
#include <cuda_runtime.h>
#include <cuda_bf16.h>
#include <math.h>
#include <float.h>

#define Bz 8
#define Cc 192
#define Nn 1568
#define NP 1664            /* 13*128 */
#define BNN (Bz*Nn)        /* 12544 = 98*128 */
#define KK 9
#define NBLK 13
#define NPAIR (NBLK*(NBLK+1)/2)     /* 91 */
#define DIST_CTAS (NPAIR*Bz)        /* 728 */
#define G1_CTAS (6*98)              /* 588 */

// smem tile geometry (128-row tiles)
#define BK 32
#define TROW_B 80                /* bytes per smem row: 40 bf16 (32 + 8 pad) */
#define TILE_B (128*TROW_B)      /* 10240 */
#define STAGE_B (4*TILE_B)       /* phase1 stage */
#define GSMEM (2*STAGE_B)        /* 81920 */

// ---- fused tail (single-pass N=192, 512 threads) ----
#define BTILE_B (192*TROW_B)              /* 15360 */
#define STG_TA  (2*TILE_B + 2*BTILE_B)    /* 51200: gh, gl, w1h, w1l */
#define OFF_H2  (2*STG_TA)                /* 102400 */
#define OFF_L2  (OFF_H2 + 6*TILE_B)       /* 163840 */
#define SM_TAIL2 (OFF_L2 + 6*TILE_B)      /* 225280 */
#define STG_TB  (2*BTILE_B)               /* 30720 */

// ---------------- scratch (static device globals; no allocation) ----------------
__device__ __align__(256) __nv_bfloat16 d_xn_hi[(size_t)Bz*NP*Cc], d_xn_lo[(size_t)Bz*NP*Cc];
__device__ __align__(256) __nv_bfloat16 d_xf_hi[(size_t)BNN*Cc],   d_xf_lo[(size_t)BNN*Cc];
__device__ __align__(256) float d_sqp[Bz*NP];
__device__ __align__(256) float d_dist[(size_t)Bz*NP*NP];
__device__ __align__(256) __nv_bfloat16 d_wuv_hi[768*Cc], d_wuv_lo[768*Cc];
__device__ __align__(256) __nv_bfloat16 d_w1_hi[256*384], d_w1_lo[256*384];
__device__ __align__(256) __nv_bfloat16 d_w2_hi[256*Cc],  d_w2_lo[256*Cc];
__device__ __align__(256) float d_c1[Cc], d_c2[Cc];
__device__ __align__(256) float d_Yt[(size_t)BNN*768];    // ALSO used as fp32 x-transpose scratch by prep
__device__ __align__(256) __nv_bfloat16 d_g_hi[(size_t)BNN*384], d_g_lo[(size_t)BNN*384];

// ---------------- PTX helpers ----------------
__device__ __forceinline__ unsigned smem_u32(const void* p) {
    unsigned a;
    asm("{ .reg .u64 t; cvta.to.shared.u64 t, %1; cvt.u32.u64 %0, t; }" : "=r"(a) : "l"(p));
    return a;
}
__device__ __forceinline__ void cpa16(unsigned s, const void* g) {
    asm volatile("cp.async.cg.shared.global [%0], [%1], 16;" :: "r"(s), "l"(g));
}
#define CP_COMMIT() asm volatile("cp.async.commit_group;" ::: "memory")
#define CP_WAIT(n)  asm volatile("cp.async.wait_group %0;" :: "n"(n) : "memory")

__device__ __forceinline__ void ldm4(unsigned* r, unsigned a) {
    asm volatile("ldmatrix.sync.aligned.m8n8.x4.shared.b16 {%0,%1,%2,%3}, [%4];"
        : "=r"(r[0]), "=r"(r[1]), "=r"(r[2]), "=r"(r[3]) : "r"(a));
}
__device__ __forceinline__ void mma_bf16(float* c, const unsigned* a, const unsigned* b) {
    asm volatile("mma.sync.aligned.m16n8k16.row.col.f32.bf16.bf16.f32 "
        "{%0,%1,%2,%3}, {%4,%5,%6,%7}, {%8,%9}, {%0,%1,%2,%3};"
        : "+f"(c[0]), "+f"(c[1]), "+f"(c[2]), "+f"(c[3])
        : "r"(a[0]), "r"(a[1]), "r"(a[2]), "r"(a[3]), "r"(b[0]), "r"(b[1]));
}

__device__ __forceinline__ void split_store(float v, __nv_bfloat16* hi, __nv_bfloat16* lo, size_t i) {
    __nv_bfloat16 h = __float2bfloat16(v);
    hi[i] = h;
    lo[i] = __float2bfloat16(v - __bfloat162float(h));
}

// ---------------- x transpose: [b][c][n] -> d_Yt scratch [(b,n)][c] (exact) ----------------
__global__ void __launch_bounds__(256) xpose(const float* __restrict__ x)
{
    __shared__ float t[32][33];
    int b = blockIdx.z;
    int n0 = blockIdx.x*32, c0 = blockIdx.y*32;
    int li = threadIdx.x & 31, wi = threadIdx.x >> 5;   // 8 warps
    float* xt = d_Yt;

    #pragma unroll
    for (int s = 0; s < 4; s++) {
        int c = c0 + wi + s*8;
        t[wi + s*8][li] = x[((size_t)(b*Cc + c))*Nn + n0 + li];
    }
    __syncthreads();
    #pragma unroll
    for (int s = 0; s < 4; s++) {
        int n = n0 + wi + s*8;
        xt[((size_t)(b*Nn + n))*Cc + c0 + li] = t[li][wi + s*8];
    }
}

// ---------------- fused prep (R10 logic; xf branch reads transposed x) ----------------
__global__ void prep_all(const float* __restrict__ pos,
                         const float* __restrict__ We, const float* __restrict__ W1,
                         const float* __restrict__ b1, const float* __restrict__ g1,
                         const float* __restrict__ bb1, const float* __restrict__ W2,
                         const float* __restrict__ b2, const float* __restrict__ g2,
                         const float* __restrict__ bb2)
{
    int blk = blockIdx.x;
    int c = threadIdx.x;              // 192 threads
    if (blk < BNN) {
        int j = blk;
        int b = j / Nn, n = j - b*Nn;
        const float* xt = d_Yt;
        float v = xt[(size_t)j*Cc + c] + pos[n*Cc + c];
        split_store(v, d_xf_hi, d_xf_lo, (size_t)j*Cc + c);

        __shared__ float red[Cc];
        __shared__ float s_nrm;
        red[c] = v*v;
        __syncthreads();
        if (c < 64) red[c] += red[c+64] + red[c+128];
        __syncthreads();
        if (c < 32) {
            float s = red[c] + red[c+32];
            #pragma unroll
            for (int o = 16; o; o >>= 1) s += __shfl_xor_sync(0xffffffffu, s, o);
            if (c == 0) s_nrm = fmaxf(sqrtf(s), 1e-12f);
        }
        __syncthreads();
        float xn = v / s_nrm;
        split_store(xn, d_xn_hi, d_xn_lo, ((size_t)b*NP + n)*Cc + c);

        red[c] = xn*xn;
        __syncthreads();
        if (c < 64) red[c] += red[c+64] + red[c+128];
        __syncthreads();
        if (c < 32) {
            float s = red[c] + red[c+32];
            #pragma unroll
            for (int o = 16; o; o >>= 1) s += __shfl_xor_sync(0xffffffffu, s, o);
            if (c == 0) d_sqp[b*NP + n] = s;
        }
    } else if (blk < BNN + 768) {
        int i = (blk - BNN)*192 + c;
        const float denom = (float)sqrt(1.0 + 1e-5);
        if (i < 768*Cc) {
            int o = i/Cc, cc = i - o*Cc;
            float v = (o < 384) ? (We[o*384 + cc] - We[o*384 + 192 + cc])
                                : We[(o-384)*384 + 192 + cc];
            split_store(v, d_wuv_hi, d_wuv_lo, i);
        }
        if (i < 256*384) {
            int o = i/384;
            float v = (o < 192) ? W1[i] * (g1[o]/denom) : 0.0f;
            split_store(v, d_w1_hi, d_w1_lo, i);
        }
        if (i < 256*192) {
            int o = i/192;
            float v = (o < 192) ? W2[i] * (g2[o]/denom) : 0.0f;
            split_store(v, d_w2_hi, d_w2_lo, i);
        }
        if (i < Cc) {
            d_c1[i] = b1[i]*(g1[i]/denom) + bb1[i];
            d_c2[i] = b2[i]*(g2[i]/denom) + bb2[i];
        }
    } else {
        int r = blk - BNN - 768;
        int b = r / (NP-Nn), pr = r - b*(NP-Nn);
        int row = Nn + pr;
        size_t i = ((size_t)b*NP + row)*Cc + c;
        d_xn_hi[i] = __float2bfloat16(0.0f);
        d_xn_lo[i] = __float2bfloat16(0.0f);
        if (c == 0) d_sqp[b*NP + row] = 1e30f;
    }
}

// ============ shared 128x128 mainloop, 256 threads (phase1) ============
template<int KDIM>
__device__ __forceinline__ void mma_mainloop(
    const __nv_bfloat16* const* srcs, const int* rbase,
    unsigned sb, int tid, int lane, int warp_m, int warp_n,
    float acc[4][4][4])
{
    constexpr int NCH = KDIM / BK;
    auto load_chunk = [&](int ch, int s) {
        unsigned so = sb + s*STAGE_B;
        int k0 = ch*BK;
        #pragma unroll
        for (int t = 0; t < 4; t++) {
            #pragma unroll
            for (int q = 0; q < 2; q++) {
                int v = tid + q*256;
                int row = v >> 2, c4 = v & 3;
                cpa16(so + t*TILE_B + row*TROW_B + c4*16,
                      srcs[t] + (size_t)(rbase[t] + row)*KDIM + k0 + c4*8);
            }
        }
    };

    load_chunk(0, 0);
    CP_COMMIT();

    #pragma unroll
    for (int ch = 0; ch < NCH; ch++) {
        if (ch + 1 < NCH) { load_chunk(ch+1, (ch+1)&1); CP_COMMIT(); CP_WAIT(1); }
        else              { CP_WAIT(0); }
        __syncthreads();

        unsigned so = sb + (ch&1)*STAGE_B;
        #pragma unroll
        for (int ks = 0; ks < 2; ks++) {
            unsigned ah[4][4], al[4][4], bh[4][2], bl[4][2];
            #pragma unroll
            for (int mt = 0; mt < 4; mt++) {
                unsigned ra = so + (warp_m*64 + mt*16 + (lane & 15))*TROW_B
                            + ks*32 + (lane >> 4)*16;
                ldm4(ah[mt], ra);
                ldm4(al[mt], ra + TILE_B);
            }
            #pragma unroll
            for (int p = 0; p < 2; p++) {
                int nrow = warp_n*32 + p*16 + (lane >> 4)*8 + (lane & 7);
                unsigned rb = so + 2*TILE_B + nrow*TROW_B + ks*32 + ((lane >> 3) & 1)*16;
                unsigned r4[4];
                ldm4(r4, rb);
                bh[2*p][0] = r4[0]; bh[2*p][1] = r4[1];
                bh[2*p+1][0] = r4[2]; bh[2*p+1][1] = r4[3];
                ldm4(r4, rb + TILE_B);
                bl[2*p][0] = r4[0]; bl[2*p][1] = r4[1];
                bl[2*p+1][0] = r4[2]; bl[2*p+1][1] = r4[3];
            }
            #pragma unroll
            for (int mt = 0; mt < 4; mt++)
                #pragma unroll
                for (int nt = 0; nt < 4; nt++) {
                    mma_bf16(acc[mt][nt], ah[mt], bh[nt]);
                    mma_bf16(acc[mt][nt], ah[mt], bl[nt]);
                    mma_bf16(acc[mt][nt], al[mt], bh[nt]);
                }
        }
        __syncthreads();
    }
}

// ---------------- phase1: dist (symmetric) + gemm1 (Yt) in ONE launch ----------------
__global__ void __launch_bounds__(256, 2) phase1()
{
    extern __shared__ char sm[];
    unsigned sb = smem_u32(sm);
    int tid = threadIdx.x, lane = tid & 31, wid = tid >> 5;
    int warp_m = wid & 1, warp_n = wid >> 1;
    int id = blockIdx.x;

    float acc[4][4][4];
    #pragma unroll
    for (int mt = 0; mt < 4; mt++)
        #pragma unroll
        for (int nt = 0; nt < 4; nt++)
            #pragma unroll
            for (int e = 0; e < 4; e++) acc[mt][nt][e] = 0.0f;

    float* stage = reinterpret_cast<float*>(sm);   // 128 x 33 floats

    if (id < DIST_CTAS) {
        int z = id / NPAIR;
        int p = id - z*NPAIR, by = 0;
        while (p >= NBLK - by) { p -= NBLK - by; by++; }
        int bx = by + p;
        int row0 = by*128, col0 = bx*128;

        size_t zo = (size_t)z*NP*Cc;
        const __nv_bfloat16* srcs[4] = {d_xn_hi + zo, d_xn_lo + zo, d_xn_hi + zo, d_xn_lo + zo};
        int rbase[4] = {row0, row0, col0, col0};
        mma_mainloop<Cc>(srcs, rbase, sb, tid, lane, warp_m, warp_n, acc);

        const float* sq = d_sqp + z*NP;
        float* dst = d_dist + (size_t)z*NP*NP;
        bool mirror = (bx != by);

        #pragma unroll 1
        for (int g = 0; g < 4; g++) {
            int cb = g*32;
            if (warp_n == g) {
                #pragma unroll
                for (int mt = 0; mt < 4; mt++) {
                    int r0 = warp_m*64 + mt*16 + (lane >> 2);
                    float s0 = sq[row0 + r0];
                    float s8 = sq[row0 + r0 + 8];
                    #pragma unroll
                    for (int nt = 0; nt < 4; nt++) {
                        int c0 = nt*8 + (lane & 3)*2;
                        stage[r0*33 + c0]     = s0 - 2.0f*acc[mt][nt][0];
                        stage[r0*33 + c0 + 1] = s0 - 2.0f*acc[mt][nt][1];
                        stage[(r0+8)*33 + c0]     = s8 - 2.0f*acc[mt][nt][2];
                        stage[(r0+8)*33 + c0 + 1] = s8 - 2.0f*acc[mt][nt][3];
                    }
                }
            }
            __syncthreads();
            {
                float sqc = sq[col0 + cb + lane];
                #pragma unroll 4
                for (int rr = 0; rr < 16; rr++) {
                    int r = wid*16 + rr;
                    dst[(size_t)(row0 + r)*NP + col0 + cb + lane] = stage[r*33 + lane] + sqc;
                }
            }
            if (mirror) {
                #pragma unroll
                for (int q = 0; q < 4; q++) {
                    int cc = wid*4 + q;
                    float sqc = sq[col0 + cb + cc];
                    #pragma unroll
                    for (int it = 0; it < 4; it++) {
                        int r = it*32 + lane;
                        dst[(size_t)(col0 + cb + cc)*NP + row0 + r] = stage[r*33 + cc] + sqc;
                    }
                }
            }
            __syncthreads();
        }
    } else {
        int t = id - DIST_CTAS;
        int by = t / 6, bx = t - by*6;
        int row0 = by*128, col0 = bx*128;

        const __nv_bfloat16* srcs[4] = {d_xf_hi, d_xf_lo, d_wuv_hi, d_wuv_lo};
        int rbase[4] = {row0, row0, col0, col0};
        mma_mainloop<Cc>(srcs, rbase, sb, tid, lane, warp_m, warp_n, acc);

        #pragma unroll 1
        for (int g = 0; g < 4; g++) {
            int cb = g*32;
            if (warp_n == g) {
                #pragma unroll
                for (int mt = 0; mt < 4; mt++) {
                    int r0 = warp_m*64 + mt*16 + (lane >> 2);
                    #pragma unroll
                    for (int nt = 0; nt < 4; nt++) {
                        int c0 = nt*8 + (lane & 3)*2;
                        stage[r0*33 + c0]     = acc[mt][nt][0];
                        stage[r0*33 + c0 + 1] = acc[mt][nt][1];
                        stage[(r0+8)*33 + c0]     = acc[mt][nt][2];
                        stage[(r0+8)*33 + c0 + 1] = acc[mt][nt][3];
                    }
                }
            }
            __syncthreads();
            #pragma unroll 4
            for (int rr = 0; rr < 16; rr++) {
                int r = wid*16 + rr;
                d_Yt[(size_t)(row0 + r)*768 + col0 + cb + lane] = stage[r*33 + lane];
            }
            __syncthreads();
        }
    }
}

// ---------------- fused tail: M=128, N=192 single pass, 512 threads ----------------
__global__ void __launch_bounds__(512) mma_tail(float* __restrict__ outp)
{
    extern __shared__ char sm[];
    unsigned sb = smem_u32(sm);
    int tid = threadIdx.x, lane = tid & 31, wid = tid >> 5;   // 16 warps
    int warp_m = wid & 3, warp_n = wid >> 2;                  // 4 x 4; warp = 32 rows x 48 cols
    int row0 = blockIdx.x*128;

    float acc[2][6][4];

    // ================= phase A: h = relu(g.W1^T + c1), K=384, single N pass =========
    #pragma unroll
    for (int mt = 0; mt < 2; mt++)
        #pragma unroll
        for (int nt = 0; nt < 6; nt++)
            #pragma unroll
            for (int e = 0; e < 4; e++) acc[mt][nt][e] = 0.0f;

    auto load_A = [&](int ch, int s) {
        unsigned so = sb + s*STG_TA;
        int k0 = ch*BK;
        int row = tid >> 2, c4 = tid & 3;   // 512 = 128 rows x 4
        cpa16(so + row*TROW_B + c4*16,
              d_g_hi + (size_t)(row0 + row)*384 + k0 + c4*8);
        cpa16(so + TILE_B + row*TROW_B + c4*16,
              d_g_lo + (size_t)(row0 + row)*384 + k0 + c4*8);
        #pragma unroll
        for (int q = 0; q < 2; q++) {
            int v = tid + q*512;
            if (v < 768) {                   // 192 rows x 4
                int r2 = v >> 2, c2 = v & 3;
                cpa16(so + 2*TILE_B + r2*TROW_B + c2*16,
                      d_w1_hi + (size_t)r2*384 + k0 + c2*8);
                cpa16(so + 2*TILE_B + BTILE_B + r2*TROW_B + c2*16,
                      d_w1_lo + (size_t)r2*384 + k0 + c2*8);
            }
        }
    };

    load_A(0, 0);
    CP_COMMIT();

    #pragma unroll
    for (int ch = 0; ch < 12; ch++) {
        if (ch + 1 < 12) { load_A(ch+1, (ch+1)&1); CP_COMMIT(); CP_WAIT(1); }
        else             { CP_WAIT(0); }
        __syncthreads();

        unsigned so = sb + (ch&1)*STG_TA;
        #pragma unroll
        for (int ks = 0; ks < 2; ks++) {
            unsigned ah[2][4], al[2][4], bh[6][2], bl[6][2];
            #pragma unroll
            for (int mt = 0; mt < 2; mt++) {
                unsigned ra = so + (warp_m*32 + mt*16 + (lane & 15))*TROW_B
                            + ks*32 + (lane >> 4)*16;
                ldm4(ah[mt], ra);
                ldm4(al[mt], ra + TILE_B);
            }
            #pragma unroll
            for (int q = 0; q < 3; q++) {
                int nrow = warp_n*48 + q*16 + (lane >> 4)*8 + (lane & 7);
                unsigned rb = so + 2*TILE_B + nrow*TROW_B + ks*32 + ((lane >> 3) & 1)*16;
                unsigned r4[4];
                ldm4(r4, rb);
                bh[2*q][0] = r4[0]; bh[2*q][1] = r4[1];
                bh[2*q+1][0] = r4[2]; bh[2*q+1][1] = r4[3];
                ldm4(r4, rb + BTILE_B);
                bl[2*q][0] = r4[0]; bl[2*q][1] = r4[1];
                bl[2*q+1][0] = r4[2]; bl[2*q+1][1] = r4[3];
            }
            #pragma unroll
            for (int mt = 0; mt < 2; mt++)
                #pragma unroll
                for (int nt = 0; nt < 6; nt++) {
                    mma_bf16(acc[mt][nt], ah[mt], bh[nt]);
                    mma_bf16(acc[mt][nt], ah[mt], bl[nt]);
                    mma_bf16(acc[mt][nt], al[mt], bh[nt]);
                }
        }
        __syncthreads();
    }

    // fragments -> persistent split-h smem tiles (ldmatrix A chunk format)
    #pragma unroll
    for (int mt = 0; mt < 2; mt++) {
        int r0 = warp_m*32 + mt*16 + (lane >> 2);
        #pragma unroll
        for (int nt = 0; nt < 6; nt++) {
            int c0 = warp_n*48 + nt*8 + (lane & 3)*2;
            #pragma unroll
            for (int e = 0; e < 4; e++) {
                int r  = r0 + ((e >> 1) << 3);
                int gc = c0 + (e & 1);
                float v = fmaxf(acc[mt][nt][e] + d_c1[gc], 0.0f);
                __nv_bfloat16 hh = __float2bfloat16(v);
                unsigned off = (unsigned)(gc >> 5)*TILE_B + r*TROW_B + (gc & 31)*2;
                *reinterpret_cast<__nv_bfloat16*>(sm + OFF_H2 + off) = hh;
                *reinterpret_cast<__nv_bfloat16*>(sm + OFF_L2 + off) =
                    __float2bfloat16(v - __bfloat162float(hh));
            }
        }
    }
    __syncthreads();

    // ================= phase B: out = relu(h.W2^T + c2) + h, K=192, single N pass ====
    #pragma unroll
    for (int mt = 0; mt < 2; mt++)
        #pragma unroll
        for (int nt = 0; nt < 6; nt++)
            #pragma unroll
            for (int e = 0; e < 4; e++) acc[mt][nt][e] = 0.0f;

    auto load_B = [&](int ch, int s) {
        unsigned so = sb + s*STG_TB;
        int k0 = ch*BK;
        #pragma unroll
        for (int q = 0; q < 2; q++) {
            int v = tid + q*512;
            if (v < 768) {
                int r2 = v >> 2, c2 = v & 3;
                cpa16(so + r2*TROW_B + c2*16,
                      d_w2_hi + (size_t)r2*Cc + k0 + c2*8);
                cpa16(so + BTILE_B + r2*TROW_B + c2*16,
                      d_w2_lo + (size_t)r2*Cc + k0 + c2*8);
            }
        }
    };

    load_B(0, 0);
    CP_COMMIT();

    #pragma unroll
    for (int ch = 0; ch < 6; ch++) {
        if (ch + 1 < 6) { load_B(ch+1, (ch+1)&1); CP_COMMIT(); CP_WAIT(1); }
        else            { CP_WAIT(0); }
        __syncthreads();

        unsigned sob = sb + (ch&1)*STG_TB;
        unsigned soa = sb + OFF_H2 + (unsigned)ch*TILE_B;
        #pragma unroll
        for (int ks = 0; ks < 2; ks++) {
            unsigned ah[2][4], al[2][4], bh[6][2], bl[6][2];
            #pragma unroll
            for (int mt = 0; mt < 2; mt++) {
                unsigned ra = soa + (warp_m*32 + mt*16 + (lane & 15))*TROW_B
                            + ks*32 + (lane >> 4)*16;
                ldm4(ah[mt], ra);
                ldm4(al[mt], ra + 6*TILE_B);
            }
            #pragma unroll
            for (int q = 0; q < 3; q++) {
                int nrow = warp_n*48 + q*16 + (lane >> 4)*8 + (lane & 7);
                unsigned rb = sob + nrow*TROW_B + ks*32 + ((lane >> 3) & 1)*16;
                unsigned r4[4];
                ldm4(r4, rb);
                bh[2*q][0] = r4[0]; bh[2*q][1] = r4[1];
                bh[2*q+1][0] = r4[2]; bh[2*q+1][1] = r4[3];
                ldm4(r4, rb + BTILE_B);
                bl[2*q][0] = r4[0]; bl[2*q][1] = r4[1];
                bl[2*q+1][0] = r4[2]; bl[2*q+1][1] = r4[3];
            }
            #pragma unroll
            for (int mt = 0; mt < 2; mt++)
                #pragma unroll
                for (int nt = 0; nt < 6; nt++) {
                    mma_bf16(acc[mt][nt], ah[mt], bh[nt]);
                    mma_bf16(acc[mt][nt], ah[mt], bl[nt]);
                    mma_bf16(acc[mt][nt], al[mt], bh[nt]);
                }
        }
        __syncthreads();
    }

    // epilogue: full 128x193 stage transpose, then coalesced scatter
    float* stage = reinterpret_cast<float*>(sm);   // 128 x 193 floats (98816 B < OFF_H2)
    #pragma unroll
    for (int mt = 0; mt < 2; mt++) {
        int r0 = warp_m*32 + mt*16 + (lane >> 2);
        #pragma unroll
        for (int nt = 0; nt < 6; nt++) {
            int c0 = warp_n*48 + nt*8 + (lane & 3)*2;
            stage[r0*193 + c0]     = acc[mt][nt][0];
            stage[r0*193 + c0 + 1] = acc[mt][nt][1];
            stage[(r0+8)*193 + c0]     = acc[mt][nt][2];
            stage[(r0+8)*193 + c0 + 1] = acc[mt][nt][3];
        }
    }
    __syncthreads();

    #pragma unroll 2
    for (int i = 0; i < 48; i++) {
        int idx = i*512 + tid;
        int gc = idx >> 7, r = idx & 127;
        int gr = row0 + r;
        unsigned off = (unsigned)(gc >> 5)*TILE_B + r*TROW_B + (gc & 31)*2;
        float sc = __bfloat162float(*reinterpret_cast<__nv_bfloat16*>(sm + OFF_H2 + off))
                 + __bfloat162float(*reinterpret_cast<__nv_bfloat16*>(sm + OFF_L2 + off));
        float v = fmaxf(stage[r*193 + gc] + d_c2[gc], 0.0f) + sc;
        int b = gr / Nn, n = gr - b*Nn;
        outp[((size_t)b*Cc + gc)*Nn + n] = v;
    }
}

// ---------------- fused top-9 + gather_max ----------------
__device__ __forceinline__ unsigned fkey32(float v) {
    unsigned u = __float_as_uint(v);
    return (u & 0x80000000u) ? ~u : (u | 0x80000000u);
}

#define TK_CAP 128

__global__ void __launch_bounds__(128) topk_gather(const float* __restrict__ be)
{
    __shared__ unsigned long long kb_s[4][TK_CAP];
    __shared__ int ids[4][KK];
    int lane = threadIdx.x & 31;
    int w    = threadIdx.x >> 5;
    int row  = blockIdx.x*4 + w;
    int b = row / Nn, n = row - b*Nn;
    const float* dr = d_dist + ((size_t)b*NP + n)*NP;
    unsigned long long* kb = kb_s[w];

    float mv = FLT_MAX;
    #pragma unroll
    for (int i = 0; i < 13; i++) {
        float4 v = reinterpret_cast<const float4*>(dr)[i*32 + lane];
        mv = fminf(mv, fminf(fminf(v.x, v.y), fminf(v.z, v.w)));
    }

    float tau = 0.0f;
    float mm = mv;
    #pragma unroll
    for (int r = 0; r < 9; r++) {
        float v = mm;
        #pragma unroll
        for (int off = 16; off; off >>= 1) v = fminf(v, __shfl_xor_sync(0xffffffffu, v, off));
        unsigned bl = __ballot_sync(0xffffffffu, mm == v);
        int src = __ffs(bl) - 1;
        if (lane == src) mm = FLT_MAX;
        tau = v;
    }

    int cnt = 0;
    #pragma unroll 1
    for (int i = 0; i < 13; i++) {
        float4 v = reinterpret_cast<const float4*>(dr)[i*32 + lane];
        int mbase = (i*32 + lane)*4;
        float vv[4] = {v.x, v.y, v.z, v.w};
        #pragma unroll
        for (int c = 0; c < 4; c++) {
            bool pr = (vv[c] <= tau);
            unsigned msk = __ballot_sync(0xffffffffu, pr);
            if (pr) {
                int pos = cnt + __popc(msk & ((1u << lane) - 1u));
                if (pos < TK_CAP)
                    kb[pos] = ((unsigned long long)fkey32(vv[c]) << 32) | (unsigned)(mbase + c);
            }
            cnt += __popc(msk);
        }
    }

    if (cnt <= TK_CAP) {
        #pragma unroll 1
        for (int r = 0; r < 9; r++) {
            unsigned long long best = ~0ULL;
            #pragma unroll
            for (int s = 0; s < 4; s++) {
                int pp = lane + s*32;
                if (pp < cnt) { unsigned long long k = kb[pp]; if (k < best) best = k; }
            }
            #pragma unroll
            for (int off = 16; off; off >>= 1) {
                unsigned long long o = __shfl_xor_sync(0xffffffffu, best, off);
                if (o < best) best = o;
            }
            #pragma unroll
            for (int s = 0; s < 4; s++) {
                int pp = lane + s*32;
                if (pp < cnt && kb[pp] == best) kb[pp] = ~0ULL;
            }
            if (lane == 0) ids[w][r] = (int)(best & 0xffffffffu);
        }
    } else if (lane == 0) {
        unsigned long long bd[9];
        #pragma unroll
        for (int s = 0; s < 9; s++) bd[s] = ~0ULL;
        unsigned long long wk = ~0ULL; int ws = 0;
        for (int m2 = 0; m2 < NP; m2++) {
            unsigned long long k = ((unsigned long long)fkey32(dr[m2]) << 32) | (unsigned)m2;
            if (k < wk) {
                bd[ws] = k;
                wk = bd[0]; ws = 0;
                #pragma unroll
                for (int s = 1; s < 9; s++) if (bd[s] > wk) { wk = bd[s]; ws = s; }
            }
        }
        #pragma unroll
        for (int s = 0; s < 9; s++) ids[w][s] = (int)(bd[s] & 0xffffffffu);
    }

    __syncthreads();

    int tid = threadIdx.x;
    #pragma unroll 1
    for (int rw = 0; rw < 4; rw++) {
        int j = blockIdx.x*4 + rw;
        int bb = j / Nn;
        int base = bb*Nn;
        int id2[9];
        #pragma unroll
        for (int k = 0; k < 9; k++) id2[k] = ids[rw][k];
        #pragma unroll
        for (int it = 0; it < 3; it++) {
            int o = it*128 + tid;
            float m = -FLT_MAX;
            #pragma unroll
            for (int k = 0; k < 9; k++)
                m = fmaxf(m, d_Yt[(size_t)(base + id2[k])*768 + 384 + o]);
            float u = d_Yt[(size_t)j*768 + o] + be[o];
            float v = fmaxf(u + m, 0.0f);
            split_store(v, d_g_hi, d_g_lo, (size_t)j*384 + o);
        }
    }
}

// ---------------- launch ----------------
extern "C" void kernel_launch(void* const* d_in, const int* in_sizes, int n_in,
                              void* d_out, int out_size)
{
    const float* x   = (const float*)d_in[0];
    const float* pos = (const float*)d_in[1];
    const float* We  = (const float*)d_in[2];
    const float* be  = (const float*)d_in[3];
    const float* W1  = (const float*)d_in[4];
    const float* b1  = (const float*)d_in[5];
    const float* g1  = (const float*)d_in[6];
    const float* bb1 = (const float*)d_in[7];
    const float* W2  = (const float*)d_in[8];
    const float* b2  = (const float*)d_in[9];
    const float* g2  = (const float*)d_in[10];
    const float* bb2 = (const float*)d_in[11];
    float* out = (float*)d_out;

    cudaFuncSetAttribute(phase1,   cudaFuncAttributeMaxDynamicSharedMemorySize, GSMEM);
    cudaFuncSetAttribute(mma_tail, cudaFuncAttributeMaxDynamicSharedMemorySize, SM_TAIL2);

    { dim3 g(49, 6, Bz); xpose<<<g, 256>>>(x); }
    prep_all<<<BNN + 768 + Bz*(NP-Nn), 192>>>(pos, We, W1, b1, g1, bb1, W2, b2, g2, bb2);
    phase1<<<DIST_CTAS + G1_CTAS, 256, GSMEM>>>();
    topk_gather<<<BNN/4, 128>>>(be);
    mma_tail<<<BNN/128, 512, SM_TAIL2>>>(out);
}

// round 16
// speedup vs baseline: 1.1646x; 1.0097x over previous
#include <cuda_runtime.h>
#include <cuda_bf16.h>
#include <math.h>
#include <float.h>

#define Bz 8
#define Cc 192
#define Nn 1568
#define NP 1664            /* 13*128 */
#define BNN (Bz*Nn)        /* 12544 = 98*128 */
#define KK 9
#define NBLK 13
#define NPAIR (NBLK*(NBLK+1)/2)     /* 91 */
#define DIST_CTAS (NPAIR*Bz)        /* 728 */
#define G1_CTAS (6*98)              /* 588 */

// smem tile geometry (128-row tiles)
#define BK 32
#define TROW_B 80                /* bytes per smem row: 40 bf16 (32 + 8 pad) */
#define TILE_B (128*TROW_B)      /* 10240 */
#define STAGE_B (4*TILE_B)       /* phase1 stage */
#define GSMEM (2*STAGE_B)        /* 81920 */

// ---- fused tail (single-pass N=192, 512 threads) ----
#define BTILE_B (192*TROW_B)              /* 15360 */
#define STG_TA  (2*TILE_B + 2*BTILE_B)    /* 51200: gh, gl, w1h, w1l */
#define OFF_H2  (2*STG_TA)                /* 102400 */
#define OFF_L2  (OFF_H2 + 6*TILE_B)       /* 163840 */
#define SM_TAIL2 (OFF_L2 + 6*TILE_B)      /* 225280 */
#define STG_TB  (2*BTILE_B)               /* 30720 */

// ---------------- scratch (static device globals; no allocation) ----------------
__device__ __align__(256) __nv_bfloat16 d_xn_hi[(size_t)Bz*NP*Cc], d_xn_lo[(size_t)Bz*NP*Cc];
__device__ __align__(256) __nv_bfloat16 d_xf_hi[(size_t)BNN*Cc],   d_xf_lo[(size_t)BNN*Cc];
__device__ __align__(256) float d_sqp[Bz*NP];
__device__ __align__(256) float d_dist[(size_t)Bz*NP*NP];
__device__ __align__(256) __nv_bfloat16 d_wuv_hi[768*Cc], d_wuv_lo[768*Cc];
__device__ __align__(256) __nv_bfloat16 d_w1_hi[256*384], d_w1_lo[256*384];
__device__ __align__(256) __nv_bfloat16 d_w2_hi[256*Cc],  d_w2_lo[256*Cc];
__device__ __align__(256) float d_c1[Cc], d_c2[Cc];
__device__ __align__(256) float d_Yt[(size_t)BNN*768];    // ALSO used as fp32 x-transpose scratch by prep
__device__ __align__(256) __nv_bfloat16 d_g_hi[(size_t)BNN*384], d_g_lo[(size_t)BNN*384];

// ---------------- PTX helpers ----------------
__device__ __forceinline__ unsigned smem_u32(const void* p) {
    unsigned a;
    asm("{ .reg .u64 t; cvta.to.shared.u64 t, %1; cvt.u32.u64 %0, t; }" : "=r"(a) : "l"(p));
    return a;
}
__device__ __forceinline__ void cpa16(unsigned s, const void* g) {
    asm volatile("cp.async.cg.shared.global [%0], [%1], 16;" :: "r"(s), "l"(g));
}
#define CP_COMMIT() asm volatile("cp.async.commit_group;" ::: "memory")
#define CP_WAIT(n)  asm volatile("cp.async.wait_group %0;" :: "n"(n) : "memory")

__device__ __forceinline__ void ldm4(unsigned* r, unsigned a) {
    asm volatile("ldmatrix.sync.aligned.m8n8.x4.shared.b16 {%0,%1,%2,%3}, [%4];"
        : "=r"(r[0]), "=r"(r[1]), "=r"(r[2]), "=r"(r[3]) : "r"(a));
}
__device__ __forceinline__ void mma_bf16(float* c, const unsigned* a, const unsigned* b) {
    asm volatile("mma.sync.aligned.m16n8k16.row.col.f32.bf16.bf16.f32 "
        "{%0,%1,%2,%3}, {%4,%5,%6,%7}, {%8,%9}, {%0,%1,%2,%3};"
        : "+f"(c[0]), "+f"(c[1]), "+f"(c[2]), "+f"(c[3])
        : "r"(a[0]), "r"(a[1]), "r"(a[2]), "r"(a[3]), "r"(b[0]), "r"(b[1]));
}

__device__ __forceinline__ void split_store(float v, __nv_bfloat16* hi, __nv_bfloat16* lo, size_t i) {
    __nv_bfloat16 h = __float2bfloat16(v);
    hi[i] = h;
    lo[i] = __float2bfloat16(v - __bfloat162float(h));
}

// ---------------- x transpose: [b][c][n] -> d_Yt scratch [(b,n)][c] (exact) ----------------
__global__ void __launch_bounds__(256) xpose(const float* __restrict__ x)
{
    __shared__ float t[32][33];
    int b = blockIdx.z;
    int n0 = blockIdx.x*32, c0 = blockIdx.y*32;
    int li = threadIdx.x & 31, wi = threadIdx.x >> 5;   // 8 warps
    float* xt = d_Yt;

    #pragma unroll
    for (int s = 0; s < 4; s++) {
        int c = c0 + wi + s*8;
        t[wi + s*8][li] = x[((size_t)(b*Cc + c))*Nn + n0 + li];
    }
    __syncthreads();
    #pragma unroll
    for (int s = 0; s < 4; s++) {
        int n = n0 + wi + s*8;
        xt[((size_t)(b*Nn + n))*Cc + c0 + li] = t[li][wi + s*8];
    }
}

// ---------------- fused prep (R10 logic; xf branch reads transposed x) ----------------
__global__ void prep_all(const float* __restrict__ pos,
                         const float* __restrict__ We, const float* __restrict__ W1,
                         const float* __restrict__ b1, const float* __restrict__ g1,
                         const float* __restrict__ bb1, const float* __restrict__ W2,
                         const float* __restrict__ b2, const float* __restrict__ g2,
                         const float* __restrict__ bb2)
{
    int blk = blockIdx.x;
    int c = threadIdx.x;              // 192 threads
    if (blk < BNN) {
        int j = blk;
        int b = j / Nn, n = j - b*Nn;
        const float* xt = d_Yt;
        float v = xt[(size_t)j*Cc + c] + pos[n*Cc + c];
        split_store(v, d_xf_hi, d_xf_lo, (size_t)j*Cc + c);

        __shared__ float red[Cc];
        __shared__ float s_nrm;
        red[c] = v*v;
        __syncthreads();
        if (c < 64) red[c] += red[c+64] + red[c+128];
        __syncthreads();
        if (c < 32) {
            float s = red[c] + red[c+32];
            #pragma unroll
            for (int o = 16; o; o >>= 1) s += __shfl_xor_sync(0xffffffffu, s, o);
            if (c == 0) s_nrm = fmaxf(sqrtf(s), 1e-12f);
        }
        __syncthreads();
        float xn = v / s_nrm;
        split_store(xn, d_xn_hi, d_xn_lo, ((size_t)b*NP + n)*Cc + c);

        red[c] = xn*xn;
        __syncthreads();
        if (c < 64) red[c] += red[c+64] + red[c+128];
        __syncthreads();
        if (c < 32) {
            float s = red[c] + red[c+32];
            #pragma unroll
            for (int o = 16; o; o >>= 1) s += __shfl_xor_sync(0xffffffffu, s, o);
            if (c == 0) d_sqp[b*NP + n] = s;
        }
    } else if (blk < BNN + 768) {
        int i = (blk - BNN)*192 + c;
        const float denom = (float)sqrt(1.0 + 1e-5);
        if (i < 768*Cc) {
            int o = i/Cc, cc = i - o*Cc;
            float v = (o < 384) ? (We[o*384 + cc] - We[o*384 + 192 + cc])
                                : We[(o-384)*384 + 192 + cc];
            split_store(v, d_wuv_hi, d_wuv_lo, i);
        }
        if (i < 256*384) {
            int o = i/384;
            float v = (o < 192) ? W1[i] * (g1[o]/denom) : 0.0f;
            split_store(v, d_w1_hi, d_w1_lo, i);
        }
        if (i < 256*192) {
            int o = i/192;
            float v = (o < 192) ? W2[i] * (g2[o]/denom) : 0.0f;
            split_store(v, d_w2_hi, d_w2_lo, i);
        }
        if (i < Cc) {
            d_c1[i] = b1[i]*(g1[i]/denom) + bb1[i];
            d_c2[i] = b2[i]*(g2[i]/denom) + bb2[i];
        }
    } else {
        int r = blk - BNN - 768;
        int b = r / (NP-Nn), pr = r - b*(NP-Nn);
        int row = Nn + pr;
        size_t i = ((size_t)b*NP + row)*Cc + c;
        d_xn_hi[i] = __float2bfloat16(0.0f);
        d_xn_lo[i] = __float2bfloat16(0.0f);
        if (c == 0) d_sqp[b*NP + row] = 1e30f;
    }
}

// ============ shared 128x128 mainloop, 256 threads (phase1) ============
template<int KDIM>
__device__ __forceinline__ void mma_mainloop(
    const __nv_bfloat16* const* srcs, const int* rbase,
    unsigned sb, int tid, int lane, int warp_m, int warp_n,
    float acc[4][4][4])
{
    constexpr int NCH = KDIM / BK;
    auto load_chunk = [&](int ch, int s) {
        unsigned so = sb + s*STAGE_B;
        int k0 = ch*BK;
        #pragma unroll
        for (int t = 0; t < 4; t++) {
            #pragma unroll
            for (int q = 0; q < 2; q++) {
                int v = tid + q*256;
                int row = v >> 2, c4 = v & 3;
                cpa16(so + t*TILE_B + row*TROW_B + c4*16,
                      srcs[t] + (size_t)(rbase[t] + row)*KDIM + k0 + c4*8);
            }
        }
    };

    load_chunk(0, 0);
    CP_COMMIT();

    #pragma unroll
    for (int ch = 0; ch < NCH; ch++) {
        if (ch + 1 < NCH) { load_chunk(ch+1, (ch+1)&1); CP_COMMIT(); CP_WAIT(1); }
        else              { CP_WAIT(0); }
        __syncthreads();

        unsigned so = sb + (ch&1)*STAGE_B;
        #pragma unroll
        for (int ks = 0; ks < 2; ks++) {
            unsigned ah[4][4], al[4][4], bh[4][2], bl[4][2];
            #pragma unroll
            for (int mt = 0; mt < 4; mt++) {
                unsigned ra = so + (warp_m*64 + mt*16 + (lane & 15))*TROW_B
                            + ks*32 + (lane >> 4)*16;
                ldm4(ah[mt], ra);
                ldm4(al[mt], ra + TILE_B);
            }
            #pragma unroll
            for (int p = 0; p < 2; p++) {
                int nrow = warp_n*32 + p*16 + (lane >> 4)*8 + (lane & 7);
                unsigned rb = so + 2*TILE_B + nrow*TROW_B + ks*32 + ((lane >> 3) & 1)*16;
                unsigned r4[4];
                ldm4(r4, rb);
                bh[2*p][0] = r4[0]; bh[2*p][1] = r4[1];
                bh[2*p+1][0] = r4[2]; bh[2*p+1][1] = r4[3];
                ldm4(r4, rb + TILE_B);
                bl[2*p][0] = r4[0]; bl[2*p][1] = r4[1];
                bl[2*p+1][0] = r4[2]; bl[2*p+1][1] = r4[3];
            }
            #pragma unroll
            for (int mt = 0; mt < 4; mt++)
                #pragma unroll
                for (int nt = 0; nt < 4; nt++) {
                    mma_bf16(acc[mt][nt], ah[mt], bh[nt]);
                    mma_bf16(acc[mt][nt], ah[mt], bl[nt]);
                    mma_bf16(acc[mt][nt], al[mt], bh[nt]);
                }
        }
        __syncthreads();
    }
}

// ---------------- phase1: dist (symmetric) + gemm1 (Yt) in ONE launch ----------------
__global__ void __launch_bounds__(256, 2) phase1()
{
    extern __shared__ char sm[];
    unsigned sb = smem_u32(sm);
    int tid = threadIdx.x, lane = tid & 31, wid = tid >> 5;
    int warp_m = wid & 1, warp_n = wid >> 1;
    int id = blockIdx.x;

    float acc[4][4][4];
    #pragma unroll
    for (int mt = 0; mt < 4; mt++)
        #pragma unroll
        for (int nt = 0; nt < 4; nt++)
            #pragma unroll
            for (int e = 0; e < 4; e++) acc[mt][nt][e] = 0.0f;

    float* stage = reinterpret_cast<float*>(sm);   // 128 x 33 floats

    if (id < DIST_CTAS) {
        int z = id / NPAIR;
        int p = id - z*NPAIR, by = 0;
        while (p >= NBLK - by) { p -= NBLK - by; by++; }
        int bx = by + p;
        int row0 = by*128, col0 = bx*128;

        size_t zo = (size_t)z*NP*Cc;
        const __nv_bfloat16* srcs[4] = {d_xn_hi + zo, d_xn_lo + zo, d_xn_hi + zo, d_xn_lo + zo};
        int rbase[4] = {row0, row0, col0, col0};
        mma_mainloop<Cc>(srcs, rbase, sb, tid, lane, warp_m, warp_n, acc);

        const float* sq = d_sqp + z*NP;
        float* dst = d_dist + (size_t)z*NP*NP;
        bool mirror = (bx != by);

        #pragma unroll 1
        for (int g = 0; g < 4; g++) {
            int cb = g*32;
            if (warp_n == g) {
                #pragma unroll
                for (int mt = 0; mt < 4; mt++) {
                    int r0 = warp_m*64 + mt*16 + (lane >> 2);
                    float s0 = sq[row0 + r0];
                    float s8 = sq[row0 + r0 + 8];
                    #pragma unroll
                    for (int nt = 0; nt < 4; nt++) {
                        int c0 = nt*8 + (lane & 3)*2;
                        stage[r0*33 + c0]     = s0 - 2.0f*acc[mt][nt][0];
                        stage[r0*33 + c0 + 1] = s0 - 2.0f*acc[mt][nt][1];
                        stage[(r0+8)*33 + c0]     = s8 - 2.0f*acc[mt][nt][2];
                        stage[(r0+8)*33 + c0 + 1] = s8 - 2.0f*acc[mt][nt][3];
                    }
                }
            }
            __syncthreads();
            {
                float sqc = sq[col0 + cb + lane];
                #pragma unroll 4
                for (int rr = 0; rr < 16; rr++) {
                    int r = wid*16 + rr;
                    dst[(size_t)(row0 + r)*NP + col0 + cb + lane] = stage[r*33 + lane] + sqc;
                }
            }
            if (mirror) {
                #pragma unroll
                for (int q = 0; q < 4; q++) {
                    int cc = wid*4 + q;
                    float sqc = sq[col0 + cb + cc];
                    #pragma unroll
                    for (int it = 0; it < 4; it++) {
                        int r = it*32 + lane;
                        dst[(size_t)(col0 + cb + cc)*NP + row0 + r] = stage[r*33 + cc] + sqc;
                    }
                }
            }
            __syncthreads();
        }
    } else {
        int t = id - DIST_CTAS;
        int by = t / 6, bx = t - by*6;
        int row0 = by*128, col0 = bx*128;

        const __nv_bfloat16* srcs[4] = {d_xf_hi, d_xf_lo, d_wuv_hi, d_wuv_lo};
        int rbase[4] = {row0, row0, col0, col0};
        mma_mainloop<Cc>(srcs, rbase, sb, tid, lane, warp_m, warp_n, acc);

        #pragma unroll 1
        for (int g = 0; g < 4; g++) {
            int cb = g*32;
            if (warp_n == g) {
                #pragma unroll
                for (int mt = 0; mt < 4; mt++) {
                    int r0 = warp_m*64 + mt*16 + (lane >> 2);
                    #pragma unroll
                    for (int nt = 0; nt < 4; nt++) {
                        int c0 = nt*8 + (lane & 3)*2;
                        stage[r0*33 + c0]     = acc[mt][nt][0];
                        stage[r0*33 + c0 + 1] = acc[mt][nt][1];
                        stage[(r0+8)*33 + c0]     = acc[mt][nt][2];
                        stage[(r0+8)*33 + c0 + 1] = acc[mt][nt][3];
                    }
                }
            }
            __syncthreads();
            #pragma unroll 4
            for (int rr = 0; rr < 16; rr++) {
                int r = wid*16 + rr;
                d_Yt[(size_t)(row0 + r)*768 + col0 + cb + lane] = stage[r*33 + lane];
            }
            __syncthreads();
        }
    }
}

// ---------------- fused tail: M=128, N=192 single pass, 512 threads ----------------
__global__ void __launch_bounds__(512) mma_tail(float* __restrict__ outp)
{
    extern __shared__ char sm[];
    unsigned sb = smem_u32(sm);
    int tid = threadIdx.x, lane = tid & 31, wid = tid >> 5;   // 16 warps
    int warp_m = wid & 3, warp_n = wid >> 2;                  // 4 x 4; warp = 32 rows x 48 cols
    int row0 = blockIdx.x*128;

    float acc[2][6][4];

    // ================= phase A: h = relu(g.W1^T + c1), K=384, single N pass =========
    #pragma unroll
    for (int mt = 0; mt < 2; mt++)
        #pragma unroll
        for (int nt = 0; nt < 6; nt++)
            #pragma unroll
            for (int e = 0; e < 4; e++) acc[mt][nt][e] = 0.0f;

    auto load_A = [&](int ch, int s) {
        unsigned so = sb + s*STG_TA;
        int k0 = ch*BK;
        int row = tid >> 2, c4 = tid & 3;   // 512 = 128 rows x 4
        cpa16(so + row*TROW_B + c4*16,
              d_g_hi + (size_t)(row0 + row)*384 + k0 + c4*8);
        cpa16(so + TILE_B + row*TROW_B + c4*16,
              d_g_lo + (size_t)(row0 + row)*384 + k0 + c4*8);
        #pragma unroll
        for (int q = 0; q < 2; q++) {
            int v = tid + q*512;
            if (v < 768) {                   // 192 rows x 4
                int r2 = v >> 2, c2 = v & 3;
                cpa16(so + 2*TILE_B + r2*TROW_B + c2*16,
                      d_w1_hi + (size_t)r2*384 + k0 + c2*8);
                cpa16(so + 2*TILE_B + BTILE_B + r2*TROW_B + c2*16,
                      d_w1_lo + (size_t)r2*384 + k0 + c2*8);
            }
        }
    };

    load_A(0, 0);
    CP_COMMIT();

    #pragma unroll
    for (int ch = 0; ch < 12; ch++) {
        if (ch + 1 < 12) { load_A(ch+1, (ch+1)&1); CP_COMMIT(); CP_WAIT(1); }
        else             { CP_WAIT(0); }
        __syncthreads();

        unsigned so = sb + (ch&1)*STG_TA;
        #pragma unroll
        for (int ks = 0; ks < 2; ks++) {
            unsigned ah[2][4], al[2][4], bh[6][2], bl[6][2];
            #pragma unroll
            for (int mt = 0; mt < 2; mt++) {
                unsigned ra = so + (warp_m*32 + mt*16 + (lane & 15))*TROW_B
                            + ks*32 + (lane >> 4)*16;
                ldm4(ah[mt], ra);
                ldm4(al[mt], ra + TILE_B);
            }
            #pragma unroll
            for (int q = 0; q < 3; q++) {
                int nrow = warp_n*48 + q*16 + (lane >> 4)*8 + (lane & 7);
                unsigned rb = so + 2*TILE_B + nrow*TROW_B + ks*32 + ((lane >> 3) & 1)*16;
                unsigned r4[4];
                ldm4(r4, rb);
                bh[2*q][0] = r4[0]; bh[2*q][1] = r4[1];
                bh[2*q+1][0] = r4[2]; bh[2*q+1][1] = r4[3];
                ldm4(r4, rb + BTILE_B);
                bl[2*q][0] = r4[0]; bl[2*q][1] = r4[1];
                bl[2*q+1][0] = r4[2]; bl[2*q+1][1] = r4[3];
            }
            #pragma unroll
            for (int mt = 0; mt < 2; mt++)
                #pragma unroll
                for (int nt = 0; nt < 6; nt++) {
                    mma_bf16(acc[mt][nt], ah[mt], bh[nt]);
                    mma_bf16(acc[mt][nt], ah[mt], bl[nt]);
                    mma_bf16(acc[mt][nt], al[mt], bh[nt]);
                }
        }
        __syncthreads();
    }

    // fragments -> persistent split-h smem tiles (ldmatrix A chunk format)
    #pragma unroll
    for (int mt = 0; mt < 2; mt++) {
        int r0 = warp_m*32 + mt*16 + (lane >> 2);
        #pragma unroll
        for (int nt = 0; nt < 6; nt++) {
            int c0 = warp_n*48 + nt*8 + (lane & 3)*2;
            #pragma unroll
            for (int e = 0; e < 4; e++) {
                int r  = r0 + ((e >> 1) << 3);
                int gc = c0 + (e & 1);
                float v = fmaxf(acc[mt][nt][e] + d_c1[gc], 0.0f);
                __nv_bfloat16 hh = __float2bfloat16(v);
                unsigned off = (unsigned)(gc >> 5)*TILE_B + r*TROW_B + (gc & 31)*2;
                *reinterpret_cast<__nv_bfloat16*>(sm + OFF_H2 + off) = hh;
                *reinterpret_cast<__nv_bfloat16*>(sm + OFF_L2 + off) =
                    __float2bfloat16(v - __bfloat162float(hh));
            }
        }
    }
    __syncthreads();

    // ================= phase B: out = relu(h.W2^T + c2) + h, K=192, single N pass ====
    #pragma unroll
    for (int mt = 0; mt < 2; mt++)
        #pragma unroll
        for (int nt = 0; nt < 6; nt++)
            #pragma unroll
            for (int e = 0; e < 4; e++) acc[mt][nt][e] = 0.0f;

    auto load_B = [&](int ch, int s) {
        unsigned so = sb + s*STG_TB;
        int k0 = ch*BK;
        #pragma unroll
        for (int q = 0; q < 2; q++) {
            int v = tid + q*512;
            if (v < 768) {
                int r2 = v >> 2, c2 = v & 3;
                cpa16(so + r2*TROW_B + c2*16,
                      d_w2_hi + (size_t)r2*Cc + k0 + c2*8);
                cpa16(so + BTILE_B + r2*TROW_B + c2*16,
                      d_w2_lo + (size_t)r2*Cc + k0 + c2*8);
            }
        }
    };

    load_B(0, 0);
    CP_COMMIT();

    #pragma unroll
    for (int ch = 0; ch < 6; ch++) {
        if (ch + 1 < 6) { load_B(ch+1, (ch+1)&1); CP_COMMIT(); CP_WAIT(1); }
        else            { CP_WAIT(0); }
        __syncthreads();

        unsigned sob = sb + (ch&1)*STG_TB;
        unsigned soa = sb + OFF_H2 + (unsigned)ch*TILE_B;
        #pragma unroll
        for (int ks = 0; ks < 2; ks++) {
            unsigned ah[2][4], al[2][4], bh[6][2], bl[6][2];
            #pragma unroll
            for (int mt = 0; mt < 2; mt++) {
                unsigned ra = soa + (warp_m*32 + mt*16 + (lane & 15))*TROW_B
                            + ks*32 + (lane >> 4)*16;
                ldm4(ah[mt], ra);
                ldm4(al[mt], ra + 6*TILE_B);
            }
            #pragma unroll
            for (int q = 0; q < 3; q++) {
                int nrow = warp_n*48 + q*16 + (lane >> 4)*8 + (lane & 7);
                unsigned rb = sob + nrow*TROW_B + ks*32 + ((lane >> 3) & 1)*16;
                unsigned r4[4];
                ldm4(r4, rb);
                bh[2*q][0] = r4[0]; bh[2*q][1] = r4[1];
                bh[2*q+1][0] = r4[2]; bh[2*q+1][1] = r4[3];
                ldm4(r4, rb + BTILE_B);
                bl[2*q][0] = r4[0]; bl[2*q][1] = r4[1];
                bl[2*q+1][0] = r4[2]; bl[2*q+1][1] = r4[3];
            }
            #pragma unroll
            for (int mt = 0; mt < 2; mt++)
                #pragma unroll
                for (int nt = 0; nt < 6; nt++) {
                    mma_bf16(acc[mt][nt], ah[mt], bh[nt]);
                    mma_bf16(acc[mt][nt], ah[mt], bl[nt]);
                    mma_bf16(acc[mt][nt], al[mt], bh[nt]);
                }
        }
        __syncthreads();
    }

    // epilogue: full 128x193 stage transpose, then coalesced scatter
    float* stage = reinterpret_cast<float*>(sm);   // 128 x 193 floats (98816 B < OFF_H2)
    #pragma unroll
    for (int mt = 0; mt < 2; mt++) {
        int r0 = warp_m*32 + mt*16 + (lane >> 2);
        #pragma unroll
        for (int nt = 0; nt < 6; nt++) {
            int c0 = warp_n*48 + nt*8 + (lane & 3)*2;
            stage[r0*193 + c0]     = acc[mt][nt][0];
            stage[r0*193 + c0 + 1] = acc[mt][nt][1];
            stage[(r0+8)*193 + c0]     = acc[mt][nt][2];
            stage[(r0+8)*193 + c0 + 1] = acc[mt][nt][3];
        }
    }
    __syncthreads();

    #pragma unroll 2
    for (int i = 0; i < 48; i++) {
        int idx = i*512 + tid;
        int gc = idx >> 7, r = idx & 127;
        int gr = row0 + r;
        unsigned off = (unsigned)(gc >> 5)*TILE_B + r*TROW_B + (gc & 31)*2;
        float sc = __bfloat162float(*reinterpret_cast<__nv_bfloat16*>(sm + OFF_H2 + off))
                 + __bfloat162float(*reinterpret_cast<__nv_bfloat16*>(sm + OFF_L2 + off));
        float v = fmaxf(stage[r*193 + gc] + d_c2[gc], 0.0f) + sc;
        int b = gr / Nn, n = gr - b*Nn;
        outp[((size_t)b*Cc + gc)*Nn + n] = v;
    }
}

// ---------------- fused top-9 + gather_max (register-cached row) ----------------
__device__ __forceinline__ unsigned fkey32(float v) {
    unsigned u = __float_as_uint(v);
    return (u & 0x80000000u) ? ~u : (u | 0x80000000u);
}

#define TK_CAP 128

__global__ void __launch_bounds__(128) topk_gather(const float* __restrict__ be)
{
    __shared__ unsigned long long kb_s[4][TK_CAP];
    __shared__ int ids[4][KK];
    int lane = threadIdx.x & 31;
    int w    = threadIdx.x >> 5;
    int row  = blockIdx.x*4 + w;
    int b = row / Nn, n = row - b*Nn;
    const float* dr = d_dist + ((size_t)b*NP + n)*NP;
    unsigned long long* kb = kb_s[w];

    // ---- pass 1: load row into registers, per-lane min ----
    float rv[52];
    float mv = FLT_MAX;
    #pragma unroll
    for (int i = 0; i < 13; i++) {
        float4 v = reinterpret_cast<const float4*>(dr)[i*32 + lane];
        rv[i*4+0] = v.x; rv[i*4+1] = v.y; rv[i*4+2] = v.z; rv[i*4+3] = v.w;
        mv = fminf(mv, fminf(fminf(v.x, v.y), fminf(v.z, v.w)));
    }

    // ---- tau = 9th smallest of 32 lane minima ----
    float tau = 0.0f;
    float mm = mv;
    #pragma unroll
    for (int r = 0; r < 9; r++) {
        float v = mm;
        #pragma unroll
        for (int off = 16; off; off >>= 1) v = fminf(v, __shfl_xor_sync(0xffffffffu, v, off));
        unsigned bl = __ballot_sync(0xffffffffu, mm == v);
        int src = __ffs(bl) - 1;
        if (lane == src) mm = FLT_MAX;
        tau = v;
    }

    // ---- pass 2: compact candidates from registers ----
    int cnt = 0;
    #pragma unroll
    for (int i = 0; i < 13; i++) {
        int mbase = (i*32 + lane)*4;
        #pragma unroll
        for (int c = 0; c < 4; c++) {
            float val = rv[i*4 + c];
            bool pr = (val <= tau);
            unsigned msk = __ballot_sync(0xffffffffu, pr);
            if (pr) {
                int pos = cnt + __popc(msk & ((1u << lane) - 1u));
                if (pos < TK_CAP)
                    kb[pos] = ((unsigned long long)fkey32(val) << 32) | (unsigned)(mbase + c);
            }
            cnt += __popc(msk);
        }
    }

    if (cnt <= TK_CAP) {
        #pragma unroll 1
        for (int r = 0; r < 9; r++) {
            unsigned long long best = ~0ULL;
            #pragma unroll
            for (int s = 0; s < 4; s++) {
                int pp = lane + s*32;
                if (pp < cnt) { unsigned long long k = kb[pp]; if (k < best) best = k; }
            }
            #pragma unroll
            for (int off = 16; off; off >>= 1) {
                unsigned long long o = __shfl_xor_sync(0xffffffffu, best, off);
                if (o < best) best = o;
            }
            #pragma unroll
            for (int s = 0; s < 4; s++) {
                int pp = lane + s*32;
                if (pp < cnt && kb[pp] == best) kb[pp] = ~0ULL;
            }
            if (lane == 0) ids[w][r] = (int)(best & 0xffffffffu);
        }
    } else if (lane == 0) {
        unsigned long long bd[9];
        #pragma unroll
        for (int s = 0; s < 9; s++) bd[s] = ~0ULL;
        unsigned long long wk = ~0ULL; int ws = 0;
        for (int m2 = 0; m2 < NP; m2++) {
            unsigned long long k = ((unsigned long long)fkey32(dr[m2]) << 32) | (unsigned)m2;
            if (k < wk) {
                bd[ws] = k;
                wk = bd[0]; ws = 0;
                #pragma unroll
                for (int s = 1; s < 9; s++) if (bd[s] > wk) { wk = bd[s]; ws = s; }
            }
        }
        #pragma unroll
        for (int s = 0; s < 9; s++) ids[w][s] = (int)(bd[s] & 0xffffffffu);
    }

    __syncthreads();

    int tid = threadIdx.x;
    #pragma unroll 1
    for (int rw = 0; rw < 4; rw++) {
        int j = blockIdx.x*4 + rw;
        int bb = j / Nn;
        int base = bb*Nn;
        int id2[9];
        #pragma unroll
        for (int k = 0; k < 9; k++) id2[k] = ids[rw][k];
        #pragma unroll
        for (int it = 0; it < 3; it++) {
            int o = it*128 + tid;
            float m = -FLT_MAX;
            #pragma unroll
            for (int k = 0; k < 9; k++)
                m = fmaxf(m, d_Yt[(size_t)(base + id2[k])*768 + 384 + o]);
            float u = d_Yt[(size_t)j*768 + o] + be[o];
            float v = fmaxf(u + m, 0.0f);
            split_store(v, d_g_hi, d_g_lo, (size_t)j*384 + o);
        }
    }
}

// ---------------- launch ----------------
extern "C" void kernel_launch(void* const* d_in, const int* in_sizes, int n_in,
                              void* d_out, int out_size)
{
    const float* x   = (const float*)d_in[0];
    const float* pos = (const float*)d_in[1];
    const float* We  = (const float*)d_in[2];
    const float* be  = (const float*)d_in[3];
    const float* W1  = (const float*)d_in[4];
    const float* b1  = (const float*)d_in[5];
    const float* g1  = (const float*)d_in[6];
    const float* bb1 = (const float*)d_in[7];
    const float* W2  = (const float*)d_in[8];
    const float* b2  = (const float*)d_in[9];
    const float* g2  = (const float*)d_in[10];
    const float* bb2 = (const float*)d_in[11];
    float* out = (float*)d_out;

    cudaFuncSetAttribute(phase1,   cudaFuncAttributeMaxDynamicSharedMemorySize, GSMEM);
    cudaFuncSetAttribute(mma_tail, cudaFuncAttributeMaxDynamicSharedMemorySize, SM_TAIL2);

    { dim3 g(49, 6, Bz); xpose<<<g, 256>>>(x); }
    prep_all<<<BNN + 768 + Bz*(NP-Nn), 192>>>(pos, We, W1, b1, g1, bb1, W2, b2, g2, bb2);
    phase1<<<DIST_CTAS + G1_CTAS, 256, GSMEM>>>();
    topk_gather<<<BNN/4, 128>>>(be);
    mma_tail<<<BNN/128, 512, SM_TAIL2>>>(out);
}